// round 2
// baseline (speedup 1.0000x reference)
#include <cuda_runtime.h>
#include <cuda_bf16.h>
#include <cstddef>

// Problem constants
#define BATCH 8192
#define NSEQ 50
#define NUM_NODES 200000
#define FEAT 64
#define TD 16
#define DH 64          // hidden / feature dim
#define G3 192         // 3*DH

// ---------------- static device scratch (no allocations allowed) ----------------
__device__ float g_P[(size_t)NUM_NODES * FEAT];        // node_raw @ W_feat (no bias)
__device__ float g_skill[NUM_NODES];                   // node_raw[:,0]
__device__ float g_GIs[(size_t)BATCH * NSEQ * G3];     // src gi (x @ W_ih^T + b_ih)
__device__ float g_GId[(size_t)BATCH * NSEQ * G3];     // dst gi

// ---------------- math helpers ----------------
__device__ __forceinline__ float cos_acc(float x) {
    // Cody-Waite range reduction (|x| up to ~1e6) then HW cos on reduced arg.
    const double TP = 6.283185307179586476925287;
    const float C1 = 6.28125f;
    const float C2 = (float)(TP - (double)C1);
    const float C3 = (float)(TP - (double)C1 - (double)((float)(TP - (double)C1)));
    const float INV2PI = 0.15915494309189535f;
    float k = rintf(x * INV2PI);
    float r = fmaf(-k, C1, x);
    r = fmaf(-k, C2, r);
    r = fmaf(-k, C3, r);
    return __cosf(r);
}

__device__ __forceinline__ float sigmoid_(float x) {
    return 1.0f / (1.0f + __expf(-x));
}
__device__ __forceinline__ float tanh_(float x) {
    float e = __expf(2.0f * x);
    return (e - 1.0f) / (e + 1.0f);
}

// ---------------- K1: node projection table ----------------
// P[n,j] = sum_k node_raw[n,k] * W_feat[k,j]; also extract skill column.
__global__ void __launch_bounds__(256) k_nodeproj(const float* __restrict__ nodef,
                                                  const float* __restrict__ Wf) {
    __shared__ float Wsm[4096];
    __shared__ float rowb[4][64];
    const int tid = threadIdx.x;
    for (int i = tid; i < 4096; i += 256) Wsm[i] = Wf[i];
    const int g = tid >> 6, j = tid & 63;
    const int n = blockIdx.x * 4 + g;
    rowb[g][j] = nodef[(size_t)n * 64 + j];
    __syncthreads();
    float acc = 0.f;
#pragma unroll
    for (int k = 0; k < 64; k++) acc = fmaf(rowb[g][k], Wsm[k * 64 + j], acc);
    g_P[(size_t)n * 64 + j] = acc;
    if (j == 0) g_skill[n] = rowb[g][0];
}

// ---------------- K2/K3: gi precompute ----------------
// One block per batch row; 50 timesteps. Thread k owns W_ih row k in registers.
// x[j] = [P gather] + e0*W_edge[j] + tenc@W_time[:,j] + s*W_struct[j] + C[j]
// gi[k] = b_ih[k] + dot(W_ih[k,:], x)
template <bool HAS_NODE>
__global__ void __launch_bounds__(192) k_gi(
    const int* __restrict__ nbr_nid, const int* __restrict__ nbr_eid,
    const float* __restrict__ nbr_ts, const float* __restrict__ interact_t,
    const int* __restrict__ other_ids, const float* __restrict__ edge_raw,
    const float* __restrict__ W_edge, const float* __restrict__ W_struct,
    const float* __restrict__ W_time, const float* __restrict__ time_w,
    const float* __restrict__ time_b, const float* __restrict__ W_ih,
    const float* __restrict__ b_ih, const float* __restrict__ b_feat,
    const float* __restrict__ b_edge, const float* __restrict__ b_time,
    const float* __restrict__ b_struct, float* __restrict__ GI) {
    const int b = blockIdx.x, tid = threadIdx.x;
    const int base = b * NSEQ;

    __shared__ __align__(16) float sP[NSEQ][64];
    __shared__ __align__(16) float xs[2][64];
    __shared__ float te[2][16];
    __shared__ int s_nid[NSEQ];
    __shared__ float s_e0[NSEQ], s_ts[NSEQ], s_sk[NSEQ];

    if (tid < 50) s_nid[tid] = nbr_nid[base + tid];
    if (tid >= 64 && tid < 114) s_ts[tid - 64] = nbr_ts[base + tid - 64];
    if (tid >= 128 && tid < 178)
        s_e0[tid - 128] = edge_raw[(size_t)nbr_eid[base + tid - 128] * 4];
    __syncthreads();

    if (HAS_NODE) {
        if (tid < 50) s_sk[tid] = g_skill[s_nid[tid]];
        for (int i = tid; i < NSEQ * 64; i += 192) {
            int tt = i >> 6, j = i & 63;
            sP[tt][j] = g_P[(size_t)s_nid[tt] * 64 + j];
        }
    }

    // per-thread constants
    float w[64];
    {
        const float4* wp = (const float4*)(W_ih + (size_t)tid * 64);
#pragma unroll
        for (int j4 = 0; j4 < 16; j4++) {
            float4 v = wp[j4];
            w[4 * j4] = v.x; w[4 * j4 + 1] = v.y; w[4 * j4 + 2] = v.z; w[4 * j4 + 3] = v.w;
        }
    }
    const float bih = b_ih[tid];
    const float tq = interact_t[b];
    const int other = other_ids[b];

    float We_r = 0.f, Ws_r = 0.f, C_r = 0.f, Wt_r[16];
    int dsk_i = 0;
    if (tid < 64) {
        We_r = W_edge[tid];
        Ws_r = W_struct[tid];
        C_r = b_edge[tid] + b_time[tid] + b_struct[tid];
        if (HAS_NODE) C_r += b_feat[tid] + b_struct[tid];
#pragma unroll
        for (int kk = 0; kk < 16; kk++) Wt_r[kk] = W_time[kk * 64 + tid];
        if (HAS_NODE) dsk_i = (int)g_skill[other];
    }
    float tw_r = 0.f, tb_r = 0.f;
    if (tid >= 64 && tid < 80) {
        tw_r = time_w[tid - 64];
        tb_r = time_b[tid - 64];
        te[0][tid - 64] = cos_acc(__fadd_rn(__fmul_rn(tq - s_ts[0], tw_r), tb_r));
    }
    __syncthreads();

    for (int t = 0; t < NSEQ; t++) {
        const int cur = t & 1;
        if (tid < 64) {
            int nid = s_nid[t];
            float s = (nid == other) ? 1.f : 0.f;
            if (HAS_NODE) s += ((int)s_sk[t] == dsk_i) ? 1.f : 0.f;
            float x = C_r;
            x = fmaf(s, Ws_r, x);
            x = fmaf(s_e0[t], We_r, x);
            if (HAS_NODE) x += sP[t][tid];
#pragma unroll
            for (int kk = 0; kk < 16; kk++) x = fmaf(te[cur][kk], Wt_r[kk], x);
            xs[cur][tid] = x;
        } else if (tid < 80 && t < NSEQ - 1) {
            te[cur ^ 1][tid - 64] =
                cos_acc(__fadd_rn(__fmul_rn(tq - s_ts[t + 1], tw_r), tb_r));
        }
        __syncthreads();
        float acc = bih;
        const float4* xp = (const float4*)xs[cur];
#pragma unroll
        for (int j4 = 0; j4 < 16; j4++) {
            float4 v = xp[j4];
            acc = fmaf(w[4 * j4], v.x, acc);
            acc = fmaf(w[4 * j4 + 1], v.y, acc);
            acc = fmaf(w[4 * j4 + 2], v.z, acc);
            acc = fmaf(w[4 * j4 + 3], v.w, acc);
        }
        GI[((size_t)(base + t)) * G3 + tid] = acc;
        // no second barrier: xs/te are double-buffered; the single barrier per
        // iteration orders gi(t) reads before x(t+2) rewrites the same buffer.
    }
}

// ---------------- K4/K5: GRU recurrence + tail + output linear ----------------
// 6 batch rows per block, 192 threads. Thread k owns W_hh row k in registers.
template <bool ADD_NODE>
__global__ void __launch_bounds__(192) k_gru(
    const float* __restrict__ GI, const float* __restrict__ W_hh,
    const float* __restrict__ b_hh, const float* __restrict__ W_out,
    const float* __restrict__ b_out, const float* __restrict__ W_time,
    const float* __restrict__ time_b, const float* __restrict__ W_edge,
    const float* __restrict__ b_edge, const float* __restrict__ b_time,
    const float* __restrict__ edge_raw, const float* __restrict__ b_feat,
    const int* __restrict__ node_ids, float* __restrict__ outp) {
    const int tid = threadIdx.x;
    const int b0 = blockIdx.x * 6;
    const int rows = min(6, BATCH - b0);

    __shared__ __align__(16) float h_sh[6 * 64];
    __shared__ __align__(16) float gh_sh[6 * G3];
    __shared__ float tail_sh[64];

    float w[64];
    {
        const float4* wp = (const float4*)(W_hh + (size_t)tid * 64);
#pragma unroll
        for (int j4 = 0; j4 < 16; j4++) {
            float4 v = wp[j4];
            w[4 * j4] = v.x; w[4 * j4 + 1] = v.y; w[4 * j4 + 2] = v.z; w[4 * j4 + 3] = v.w;
        }
    }
    const float bhh = b_hh[tid];

    for (int i = tid; i < 6 * 64; i += 192) h_sh[i] = 0.f;
    if (tid < 64) {
        float tl = b_time[tid] + b_edge[tid] + edge_raw[0] * W_edge[tid];
        if (ADD_NODE) tl += b_feat[tid];
#pragma unroll
        for (int kk = 0; kk < 16; kk++)
            tl = fmaf(cos_acc(time_b[kk]), W_time[kk * 64 + tid], tl);
        tail_sh[tid] = tl;
    }
    __syncthreads();

    const int r1 = tid >> 6, j1 = tid & 63;
    const int r2 = r1 + 3, j2 = j1;
    const bool a1 = (r1 < rows), a2 = (r2 < rows);
    const float* gi1 = GI + ((size_t)(b0 + r1) * NSEQ) * G3 + j1;
    const float* gi2 = GI + ((size_t)(b0 + (a2 ? r2 : 0)) * NSEQ) * G3 + j2;

    for (int t = 0; t < NSEQ; t++) {
        // prefetch gi for the combine phase (hides DRAM latency behind gh FMAs)
        float g10 = 0.f, g11 = 0.f, g12 = 0.f, g20 = 0.f, g21 = 0.f, g22 = 0.f;
        const size_t off = (size_t)t * G3;
        if (a1) { g10 = gi1[off]; g11 = gi1[off + 64]; g12 = gi1[off + 128]; }
        if (a2) { g20 = gi2[off]; g21 = gi2[off + 64]; g22 = gi2[off + 128]; }

        // gh[r][k] = b_hh[k] + dot(W_hh[k,:], h[r])
#pragma unroll
        for (int r = 0; r < 6; r++) {
            if (r < rows) {
                float acc = bhh;
                const float4* hp = (const float4*)(h_sh + r * 64);
#pragma unroll
                for (int j4 = 0; j4 < 16; j4++) {
                    float4 v = hp[j4];
                    acc = fmaf(w[4 * j4], v.x, acc);
                    acc = fmaf(w[4 * j4 + 1], v.y, acc);
                    acc = fmaf(w[4 * j4 + 2], v.z, acc);
                    acc = fmaf(w[4 * j4 + 3], v.w, acc);
                }
                gh_sh[r * G3 + tid] = acc;
            }
        }
        __syncthreads();
        if (a1) {
            float rg = sigmoid_(g10 + gh_sh[r1 * G3 + j1]);
            float z = sigmoid_(g11 + gh_sh[r1 * G3 + 64 + j1]);
            float n = tanh_(fmaf(rg, gh_sh[r1 * G3 + 128 + j1], g12));
            float hold = h_sh[r1 * 64 + j1];
            h_sh[r1 * 64 + j1] = (1.f - z) * n + z * hold;
        }
        if (a2) {
            float rg = sigmoid_(g20 + gh_sh[r2 * G3 + j2]);
            float z = sigmoid_(g21 + gh_sh[r2 * G3 + 64 + j2]);
            float n = tanh_(fmaf(rg, gh_sh[r2 * G3 + 128 + j2], g22));
            float hold = h_sh[r2 * 64 + j2];
            h_sh[r2 * 64 + j2] = (1.f - z) * n + z * hold;
        }
        __syncthreads();
    }

    // emb = h + tail (+ P[node] for dst) staged into gh_sh (reused as emb[6][64])
    if (a1) {
        float e = h_sh[r1 * 64 + j1] + tail_sh[j1];
        if (ADD_NODE) e += g_P[(size_t)node_ids[b0 + r1] * 64 + j1];
        gh_sh[r1 * 64 + j1] = e;
    }
    if (a2) {
        float e = h_sh[r2 * 64 + j2] + tail_sh[j2];
        if (ADD_NODE) e += g_P[(size_t)node_ids[b0 + r2] * 64 + j2];
        gh_sh[r2 * 64 + j2] = e;
    }
    __syncthreads();

    // out = emb @ W_out + b_out
    if (a1) {
        float acc = b_out[j1];
        const float* em = gh_sh + r1 * 64;
#pragma unroll 8
        for (int m = 0; m < 64; m++) acc = fmaf(em[m], W_out[m * 64 + j1], acc);
        outp[(size_t)(b0 + r1) * 64 + j1] = acc;
    }
    if (a2) {
        float acc = b_out[j2];
        const float* em = gh_sh + r2 * 64;
#pragma unroll 8
        for (int m = 0; m < 64; m++) acc = fmaf(em[m], W_out[m * 64 + j2], acc);
        outp[(size_t)(b0 + r2) * 64 + j2] = acc;
    }
}

// ---------------- launch ----------------
extern "C" void kernel_launch(void* const* d_in, const int* in_sizes, int n_in,
                              void* d_out, int out_size) {
    const float* node_raw = (const float*)d_in[0];
    const float* edge_raw = (const float*)d_in[1];
    const int* src_ids = (const int*)d_in[2];
    const int* dst_ids = (const int*)d_in[3];
    const float* t_int = (const float*)d_in[4];
    const int* s_nnid = (const int*)d_in[5];
    const int* s_neid = (const int*)d_in[6];
    const float* s_nts = (const float*)d_in[7];
    const int* d_nnid = (const int*)d_in[8];
    const int* d_neid = (const int*)d_in[9];
    const float* d_nts = (const float*)d_in[10];
    const float* W_feat = (const float*)d_in[11];
    const float* b_feat = (const float*)d_in[12];
    const float* W_edge = (const float*)d_in[13];
    const float* b_edge = (const float*)d_in[14];
    const float* W_time = (const float*)d_in[15];
    const float* b_time = (const float*)d_in[16];
    const float* W_struct = (const float*)d_in[17];
    const float* b_struct = (const float*)d_in[18];
    const float* W_out = (const float*)d_in[19];
    const float* b_out = (const float*)d_in[20];
    const float* time_w = (const float*)d_in[21];
    const float* time_b = (const float*)d_in[22];
    const float* sWih = (const float*)d_in[23];
    const float* sWhh = (const float*)d_in[24];
    const float* sbih = (const float*)d_in[25];
    const float* sbhh = (const float*)d_in[26];
    const float* dWih = (const float*)d_in[27];
    const float* dWhh = (const float*)d_in[28];
    const float* dbih = (const float*)d_in[29];
    const float* dbhh = (const float*)d_in[30];

    float* out = (float*)d_out;

    float* GIs_p; cudaGetSymbolAddress((void**)&GIs_p, g_GIs);
    float* GId_p; cudaGetSymbolAddress((void**)&GId_p, g_GId);

    // K1: node projection table
    k_nodeproj<<<NUM_NODES / 4, 256>>>(node_raw, W_feat);

    // K2: src gi (node feats + skill + co), other = dst node ids
    k_gi<true><<<BATCH, 192>>>(s_nnid, s_neid, s_nts, t_int, dst_ids, edge_raw,
                               W_edge, W_struct, W_time, time_w, time_b,
                               sWih, sbih, b_feat, b_edge, b_time, b_struct, GIs_p);
    // K3: dst gi (edge+time+co only), other = src node ids
    k_gi<false><<<BATCH, 192>>>(d_nnid, d_neid, d_nts, t_int, src_ids, edge_raw,
                                W_edge, W_struct, W_time, time_w, time_b,
                                dWih, dbih, b_feat, b_edge, b_time, b_struct, GId_p);

    const int gru_grid = (BATCH + 5) / 6;
    // K4: src GRU -> out[0 : B*64]
    k_gru<false><<<gru_grid, 192>>>(GIs_p, sWhh, sbhh, W_out, b_out, W_time,
                                    time_b, W_edge, b_edge, b_time, edge_raw,
                                    b_feat, nullptr, out);
    // K5: dst GRU (+ P[dst]+b_feat) -> out[B*64 : 2*B*64]
    k_gru<true><<<gru_grid, 192>>>(GId_p, dWhh, dbhh, W_out, b_out, W_time,
                                   time_b, W_edge, b_edge, b_time, edge_raw,
                                   b_feat, dst_ids, out + (size_t)BATCH * 64);
}

// round 3
// speedup vs baseline: 1.0423x; 1.0423x over previous
#include <cuda_runtime.h>
#include <cuda_bf16.h>
#include <cstddef>
#include <cstdint>

// Problem constants
#define BATCH 8192
#define NSEQ 50
#define NUM_NODES 200000
#define FEAT 64
#define TD 16
#define DH 64          // hidden / feature dim
#define G3 192         // 3*DH

typedef unsigned long long u64;

// ---------------- static device scratch (no allocations allowed) ----------------
__device__ float g_P[(size_t)NUM_NODES * FEAT];        // node_raw @ W_feat (no bias)
__device__ float g_skill[NUM_NODES];                   // node_raw[:,0]
__device__ float g_GIs[(size_t)BATCH * NSEQ * G3];     // src gi (x @ W_ih^T + b_ih)
__device__ float g_GId[(size_t)BATCH * NSEQ * G3];     // dst gi

// ---------------- packed f32x2 helpers ----------------
__device__ __forceinline__ u64 pack2(float lo, float hi) {
    u64 d; asm("mov.b64 %0, {%1, %2};" : "=l"(d) : "f"(lo), "f"(hi)); return d;
}
__device__ __forceinline__ void unpack2(u64 v, float& lo, float& hi) {
    asm("mov.b64 {%0, %1}, %2;" : "=f"(lo), "=f"(hi) : "l"(v));
}
__device__ __forceinline__ u64 ffma2(u64 a, u64 b, u64 c) {
    u64 d; asm("fma.rn.f32x2 %0, %1, %2, %3;" : "=l"(d) : "l"(a), "l"(b), "l"(c));
    return d;
}
__device__ __forceinline__ void lds_v2u64(uint32_t addr, u64& a, u64& b) {
    asm volatile("ld.shared.v2.b64 {%0, %1}, [%2];" : "=l"(a), "=l"(b) : "r"(addr));
}
__device__ __forceinline__ u64 lds_u64(uint32_t addr) {
    u64 a; asm volatile("ld.shared.b64 %0, [%1];" : "=l"(a) : "r"(addr)); return a;
}

// ---------------- math helpers ----------------
__device__ __forceinline__ float cos_acc(float x) {
    // Cody-Waite range reduction (|x| up to ~1e6) then HW cos on reduced arg.
    const double TP = 6.283185307179586476925287;
    const float C1 = 6.28125f;
    const float C2 = (float)(TP - (double)C1);
    const float C3 = (float)(TP - (double)C1 - (double)((float)(TP - (double)C1)));
    const float INV2PI = 0.15915494309189535f;
    float k = rintf(x * INV2PI);
    float r = fmaf(-k, C1, x);
    r = fmaf(-k, C2, r);
    r = fmaf(-k, C3, r);
    return __cosf(r);
}

__device__ __forceinline__ float sigmoid_(float x) {
    return 1.0f / (1.0f + __expf(-x));
}
__device__ __forceinline__ float tanh_(float x) {
    float e = __expf(2.0f * x);
    return (e - 1.0f) / (e + 1.0f);
}

// ---------------- K1: node projection table ----------------
__global__ void __launch_bounds__(256) k_nodeproj(const float* __restrict__ nodef,
                                                  const float* __restrict__ Wf) {
    __shared__ float Wsm[4096];
    __shared__ __align__(16) float rowb[4][64];
    const int tid = threadIdx.x;
    for (int i = tid; i < 4096; i += 256) Wsm[i] = Wf[i];
    const int g = tid >> 6, j = tid & 63;
    const int n = blockIdx.x * 4 + g;
    rowb[g][j] = nodef[(size_t)n * 64 + j];
    __syncthreads();
    float acc = 0.f;
#pragma unroll
    for (int k = 0; k < 64; k++) acc = fmaf(rowb[g][k], Wsm[k * 64 + j], acc);
    g_P[(size_t)n * 64 + j] = acc;
    if (j == 0) g_skill[n] = rowb[g][0];
}

// ---------------- K2/K3: gi precompute ----------------
// One block per batch row; 50 timesteps. Thread k owns W_ih row k (packed f32x2).
template <bool HAS_NODE>
__global__ void __launch_bounds__(192) k_gi(
    const int* __restrict__ nbr_nid, const int* __restrict__ nbr_eid,
    const float* __restrict__ nbr_ts, const float* __restrict__ interact_t,
    const int* __restrict__ other_ids, const float* __restrict__ edge_raw,
    const float* __restrict__ W_edge, const float* __restrict__ W_struct,
    const float* __restrict__ W_time, const float* __restrict__ time_w,
    const float* __restrict__ time_b, const float* __restrict__ W_ih,
    const float* __restrict__ b_ih, const float* __restrict__ b_feat,
    const float* __restrict__ b_edge, const float* __restrict__ b_time,
    const float* __restrict__ b_struct, float* __restrict__ GI) {
    const int b = blockIdx.x, tid = threadIdx.x;
    const int base = b * NSEQ;

    __shared__ __align__(16) float sP[NSEQ][64];
    __shared__ __align__(16) float xs[2][64];
    __shared__ __align__(16) float te[2][16];
    __shared__ int s_nid[NSEQ];
    __shared__ float s_e0[NSEQ], s_ts[NSEQ], s_sk[NSEQ];

    if (tid < 50) s_nid[tid] = nbr_nid[base + tid];
    if (tid >= 64 && tid < 114) s_ts[tid - 64] = nbr_ts[base + tid - 64];
    if (tid >= 128 && tid < 178)
        s_e0[tid - 128] = edge_raw[(size_t)nbr_eid[base + tid - 128] * 4];
    __syncthreads();

    if (HAS_NODE) {
        if (tid < 50) s_sk[tid] = g_skill[s_nid[tid]];
        for (int i = tid; i < NSEQ * 64; i += 192) {
            int tt = i >> 6, j = i & 63;
            sP[tt][j] = g_P[(size_t)s_nid[tt] * 64 + j];
        }
    }

    // per-thread constants: W_ih row packed into 32 u64
    u64 w2[32];
    {
        const float4* wp = (const float4*)(W_ih + (size_t)tid * 64);
#pragma unroll
        for (int j4 = 0; j4 < 16; j4++) {
            float4 v = wp[j4];
            w2[2 * j4] = pack2(v.x, v.y);
            w2[2 * j4 + 1] = pack2(v.z, v.w);
        }
    }
    const float bih = b_ih[tid];
    const float tq = interact_t[b];
    const int other = other_ids[b];

    const uint32_t xs_base = (uint32_t)__cvta_generic_to_shared(xs);
    const uint32_t te_base = (uint32_t)__cvta_generic_to_shared(te);

    float We_r = 0.f, Ws_r = 0.f, C_r = 0.f;
    u64 Wt2[8];
    int dsk_i = 0;
    if (tid < 64) {
        We_r = W_edge[tid];
        Ws_r = W_struct[tid];
        C_r = b_edge[tid] + b_time[tid] + b_struct[tid];
        if (HAS_NODE) C_r += b_feat[tid] + b_struct[tid];
#pragma unroll
        for (int m = 0; m < 8; m++)
            Wt2[m] = pack2(W_time[(2 * m) * 64 + tid], W_time[(2 * m + 1) * 64 + tid]);
        if (HAS_NODE) dsk_i = (int)g_skill[other];
    }
    float tw_r = 0.f, tb_r = 0.f;
    if (tid >= 64 && tid < 80) {
        tw_r = time_w[tid - 64];
        tb_r = time_b[tid - 64];
        te[0][tid - 64] = cos_acc(__fadd_rn(__fmul_rn(tq - s_ts[0], tw_r), tb_r));
    }
    __syncthreads();

    for (int t = 0; t < NSEQ; t++) {
        const int cur = t & 1;
        if (tid < 64) {
            int nid = s_nid[t];
            float s = (nid == other) ? 1.f : 0.f;
            if (HAS_NODE) s += ((int)s_sk[t] == dsk_i) ? 1.f : 0.f;
            float x = C_r;
            x = fmaf(s, Ws_r, x);
            x = fmaf(s_e0[t], We_r, x);
            if (HAS_NODE) x += sP[t][tid];
            // time dot via packed FFMA2
            u64 acc2 = 0ull;
            const uint32_t ta = te_base + (uint32_t)cur * 64;
#pragma unroll
            for (int m = 0; m < 8; m++) acc2 = ffma2(Wt2[m], lds_u64(ta + m * 8), acc2);
            float lo, hi; unpack2(acc2, lo, hi);
            xs[cur][tid] = x + lo + hi;
        } else if (tid < 80 && t < NSEQ - 1) {
            te[cur ^ 1][tid - 64] =
                cos_acc(__fadd_rn(__fmul_rn(tq - s_ts[t + 1], tw_r), tb_r));
        }
        __syncthreads();
        // gi[k] = b_ih + dot(W_ih[k,:], x)  — 32 FFMA2 per thread
        u64 acc2 = 0ull;
        const uint32_t xa = xs_base + (uint32_t)cur * 256;
#pragma unroll
        for (int j = 0; j < 16; j++) {
            u64 p, q;
            lds_v2u64(xa + j * 16, p, q);
            acc2 = ffma2(w2[2 * j], p, acc2);
            acc2 = ffma2(w2[2 * j + 1], q, acc2);
        }
        float lo, hi; unpack2(acc2, lo, hi);
        GI[((size_t)(base + t)) * G3 + tid] = bih + lo + hi;
        // single barrier per t: xs/te double-buffered.
    }
}

// ---------------- K4/K5: GRU recurrence + tail + output linear ----------------
template <bool ADD_NODE>
__global__ void __launch_bounds__(192) k_gru(
    const float* __restrict__ GI, const float* __restrict__ W_hh,
    const float* __restrict__ b_hh, const float* __restrict__ W_out,
    const float* __restrict__ b_out, const float* __restrict__ W_time,
    const float* __restrict__ time_b, const float* __restrict__ W_edge,
    const float* __restrict__ b_edge, const float* __restrict__ b_time,
    const float* __restrict__ edge_raw, const float* __restrict__ b_feat,
    const int* __restrict__ node_ids, float* __restrict__ outp) {
    const int tid = threadIdx.x;
    const int b0 = blockIdx.x * 6;
    const int rows = min(6, BATCH - b0);

    __shared__ __align__(16) float h_sh[6 * 64];
    __shared__ __align__(16) float gh_sh[6 * G3];
    __shared__ float tail_sh[64];

    u64 w2[32];
    {
        const float4* wp = (const float4*)(W_hh + (size_t)tid * 64);
#pragma unroll
        for (int j4 = 0; j4 < 16; j4++) {
            float4 v = wp[j4];
            w2[2 * j4] = pack2(v.x, v.y);
            w2[2 * j4 + 1] = pack2(v.z, v.w);
        }
    }
    const float bhh = b_hh[tid];
    const uint32_t h_base = (uint32_t)__cvta_generic_to_shared(h_sh);

    for (int i = tid; i < 6 * 64; i += 192) h_sh[i] = 0.f;
    if (tid < 64) {
        float tl = b_time[tid] + b_edge[tid] + edge_raw[0] * W_edge[tid];
        if (ADD_NODE) tl += b_feat[tid];
#pragma unroll
        for (int kk = 0; kk < 16; kk++)
            tl = fmaf(cos_acc(time_b[kk]), W_time[kk * 64 + tid], tl);
        tail_sh[tid] = tl;
    }
    __syncthreads();

    const int r1 = tid >> 6, j1 = tid & 63;
    const int r2 = r1 + 3, j2 = j1;
    const bool a1 = (r1 < rows), a2 = (r2 < rows);
    const float* gi1 = GI + ((size_t)(b0 + r1) * NSEQ) * G3 + j1;
    const float* gi2 = GI + ((size_t)(b0 + (a2 ? r2 : 0)) * NSEQ) * G3 + j2;

    for (int t = 0; t < NSEQ; t++) {
        // prefetch gi for the combine phase
        float g10 = 0.f, g11 = 0.f, g12 = 0.f, g20 = 0.f, g21 = 0.f, g22 = 0.f;
        const size_t off = (size_t)t * G3;
        if (a1) { g10 = gi1[off]; g11 = gi1[off + 64]; g12 = gi1[off + 128]; }
        if (a2) { g20 = gi2[off]; g21 = gi2[off + 64]; g22 = gi2[off + 128]; }

        // gh[r][k] = b_hh[k] + dot(W_hh[k,:], h[r])  — 32 FFMA2 per row
#pragma unroll
        for (int r = 0; r < 6; r++) {
            if (r < rows) {
                u64 acc2 = 0ull;
                const uint32_t ha = h_base + (uint32_t)r * 256;
#pragma unroll
                for (int j = 0; j < 16; j++) {
                    u64 p, q;
                    lds_v2u64(ha + j * 16, p, q);
                    acc2 = ffma2(w2[2 * j], p, acc2);
                    acc2 = ffma2(w2[2 * j + 1], q, acc2);
                }
                float lo, hi; unpack2(acc2, lo, hi);
                gh_sh[r * G3 + tid] = bhh + lo + hi;
            }
        }
        __syncthreads();
        if (a1) {
            float rg = sigmoid_(g10 + gh_sh[r1 * G3 + j1]);
            float z = sigmoid_(g11 + gh_sh[r1 * G3 + 64 + j1]);
            float n = tanh_(fmaf(rg, gh_sh[r1 * G3 + 128 + j1], g12));
            float hold = h_sh[r1 * 64 + j1];
            h_sh[r1 * 64 + j1] = (1.f - z) * n + z * hold;
        }
        if (a2) {
            float rg = sigmoid_(g20 + gh_sh[r2 * G3 + j2]);
            float z = sigmoid_(g21 + gh_sh[r2 * G3 + 64 + j2]);
            float n = tanh_(fmaf(rg, gh_sh[r2 * G3 + 128 + j2], g22));
            float hold = h_sh[r2 * 64 + j2];
            h_sh[r2 * 64 + j2] = (1.f - z) * n + z * hold;
        }
        __syncthreads();
    }

    // emb = h + tail (+ P[node] for dst) staged into gh_sh
    if (a1) {
        float e = h_sh[r1 * 64 + j1] + tail_sh[j1];
        if (ADD_NODE) e += g_P[(size_t)node_ids[b0 + r1] * 64 + j1];
        gh_sh[r1 * 64 + j1] = e;
    }
    if (a2) {
        float e = h_sh[r2 * 64 + j2] + tail_sh[j2];
        if (ADD_NODE) e += g_P[(size_t)node_ids[b0 + r2] * 64 + j2];
        gh_sh[r2 * 64 + j2] = e;
    }
    __syncthreads();

    // out = emb @ W_out + b_out
    if (a1) {
        float acc = b_out[j1];
        const float* em = gh_sh + r1 * 64;
#pragma unroll 8
        for (int m = 0; m < 64; m++) acc = fmaf(em[m], W_out[m * 64 + j1], acc);
        outp[(size_t)(b0 + r1) * 64 + j1] = acc;
    }
    if (a2) {
        float acc = b_out[j2];
        const float* em = gh_sh + r2 * 64;
#pragma unroll 8
        for (int m = 0; m < 64; m++) acc = fmaf(em[m], W_out[m * 64 + j2], acc);
        outp[(size_t)(b0 + r2) * 64 + j2] = acc;
    }
}

// ---------------- launch ----------------
extern "C" void kernel_launch(void* const* d_in, const int* in_sizes, int n_in,
                              void* d_out, int out_size) {
    const float* node_raw = (const float*)d_in[0];
    const float* edge_raw = (const float*)d_in[1];
    const int* src_ids = (const int*)d_in[2];
    const int* dst_ids = (const int*)d_in[3];
    const float* t_int = (const float*)d_in[4];
    const int* s_nnid = (const int*)d_in[5];
    const int* s_neid = (const int*)d_in[6];
    const float* s_nts = (const float*)d_in[7];
    const int* d_nnid = (const int*)d_in[8];
    const int* d_neid = (const int*)d_in[9];
    const float* d_nts = (const float*)d_in[10];
    const float* W_feat = (const float*)d_in[11];
    const float* b_feat = (const float*)d_in[12];
    const float* W_edge = (const float*)d_in[13];
    const float* b_edge = (const float*)d_in[14];
    const float* W_time = (const float*)d_in[15];
    const float* b_time = (const float*)d_in[16];
    const float* W_struct = (const float*)d_in[17];
    const float* b_struct = (const float*)d_in[18];
    const float* W_out = (const float*)d_in[19];
    const float* b_out = (const float*)d_in[20];
    const float* time_w = (const float*)d_in[21];
    const float* time_b = (const float*)d_in[22];
    const float* sWih = (const float*)d_in[23];
    const float* sWhh = (const float*)d_in[24];
    const float* sbih = (const float*)d_in[25];
    const float* sbhh = (const float*)d_in[26];
    const float* dWih = (const float*)d_in[27];
    const float* dWhh = (const float*)d_in[28];
    const float* dbih = (const float*)d_in[29];
    const float* dbhh = (const float*)d_in[30];

    float* out = (float*)d_out;

    float* GIs_p; cudaGetSymbolAddress((void**)&GIs_p, g_GIs);
    float* GId_p; cudaGetSymbolAddress((void**)&GId_p, g_GId);

    // K1: node projection table
    k_nodeproj<<<NUM_NODES / 4, 256>>>(node_raw, W_feat);

    // K2: src gi (node feats + skill + co), other = dst node ids
    k_gi<true><<<BATCH, 192>>>(s_nnid, s_neid, s_nts, t_int, dst_ids, edge_raw,
                               W_edge, W_struct, W_time, time_w, time_b,
                               sWih, sbih, b_feat, b_edge, b_time, b_struct, GIs_p);
    // K3: dst gi (edge+time+co only), other = src node ids
    k_gi<false><<<BATCH, 192>>>(d_nnid, d_neid, d_nts, t_int, src_ids, edge_raw,
                                W_edge, W_struct, W_time, time_w, time_b,
                                dWih, dbih, b_feat, b_edge, b_time, b_struct, GId_p);

    const int gru_grid = (BATCH + 5) / 6;
    // K4: src GRU -> out[0 : B*64]
    k_gru<false><<<gru_grid, 192>>>(GIs_p, sWhh, sbhh, W_out, b_out, W_time,
                                    time_b, W_edge, b_edge, b_time, edge_raw,
                                    b_feat, nullptr, out);
    // K5: dst GRU (+ P[dst]+b_feat) -> out[B*64 : 2*B*64]
    k_gru<true><<<gru_grid, 192>>>(GId_p, dWhh, dbhh, W_out, b_out, W_time,
                                   time_b, W_edge, b_edge, b_time, edge_raw,
                                   b_feat, dst_ids, out + (size_t)BATCH * 64);
}

// round 4
// speedup vs baseline: 1.0926x; 1.0483x over previous
#include <cuda_runtime.h>
#include <cuda_bf16.h>
#include <cstddef>
#include <cstdint>

// Problem constants
#define BATCH 8192
#define NSEQ 50
#define NUM_NODES 200000
#define FEAT 64
#define TD 16
#define DH 64          // hidden / feature dim
#define G3 192         // 3*DH
#define GRWS 9         // batch rows per k_gru block

typedef unsigned long long u64;

// ---------------- static device scratch (no allocations allowed) ----------------
__device__ float g_P[(size_t)NUM_NODES * FEAT];        // node_raw @ W_feat (no bias)
__device__ float g_skill[NUM_NODES];                   // node_raw[:,0]
__device__ float g_GIs[(size_t)BATCH * NSEQ * G3];     // src gi (x @ W_ih^T + b_ih)
__device__ float g_GId[(size_t)BATCH * NSEQ * G3];     // dst gi

// ---------------- packed f32x2 helpers ----------------
__device__ __forceinline__ u64 pack2(float lo, float hi) {
    u64 d; asm("mov.b64 %0, {%1, %2};" : "=l"(d) : "f"(lo), "f"(hi)); return d;
}
__device__ __forceinline__ void unpack2(u64 v, float& lo, float& hi) {
    asm("mov.b64 {%0, %1}, %2;" : "=f"(lo), "=f"(hi) : "l"(v));
}
__device__ __forceinline__ u64 ffma2(u64 a, u64 b, u64 c) {
    u64 d; asm("fma.rn.f32x2 %0, %1, %2, %3;" : "=l"(d) : "l"(a), "l"(b), "l"(c));
    return d;
}
__device__ __forceinline__ void lds_v2u64(uint32_t addr, u64& a, u64& b) {
    asm volatile("ld.shared.v2.b64 {%0, %1}, [%2];" : "=l"(a), "=l"(b) : "r"(addr));
}

// ---------------- math helpers ----------------
__device__ __forceinline__ float cos_acc(float x) {
    // Cody-Waite range reduction then HW cos on reduced arg.
    const double TP = 6.283185307179586476925287;
    const float C1 = 6.28125f;
    const float C2 = (float)(TP - (double)C1);
    const float C3 = (float)(TP - (double)C1 - (double)((float)(TP - (double)C1)));
    const float INV2PI = 0.15915494309189535f;
    float k = rintf(x * INV2PI);
    float r = fmaf(-k, C1, x);
    r = fmaf(-k, C2, r);
    r = fmaf(-k, C3, r);
    return __cosf(r);
}

__device__ __forceinline__ float sigmoid_(float x) {
    return 1.0f / (1.0f + __expf(-x));
}
__device__ __forceinline__ float tanh_(float x) {
    float e = __expf(2.0f * x);
    return (e - 1.0f) / (e + 1.0f);
}

// ---------------- K1: node projection table ----------------
__global__ void __launch_bounds__(256) k_nodeproj(const float* __restrict__ nodef,
                                                  const float* __restrict__ Wf) {
    __shared__ float Wsm[4096];
    __shared__ __align__(16) float rowb[4][64];
    const int tid = threadIdx.x;
    for (int i = tid; i < 4096; i += 256) Wsm[i] = Wf[i];
    const int g = tid >> 6, j = tid & 63;
    const int n = blockIdx.x * 4 + g;
    rowb[g][j] = nodef[(size_t)n * 64 + j];
    __syncthreads();
    float acc = 0.f;
#pragma unroll
    for (int k = 0; k < 64; k++) acc = fmaf(rowb[g][k], Wsm[k * 64 + j], acc);
    g_P[(size_t)n * 64 + j] = acc;
    if (j == 0) g_skill[n] = rowb[g][0];
}

// ---------------- K2/K3: gi precompute (barrier-free GEMV phase) ----------------
// One block per batch row. Phase A: gathers + time encodings. Phase B: X[50][64].
// Phase C: thread k owns W_ih row k; 50 independent dots, no barriers.
template <bool HAS_NODE>
__global__ void __launch_bounds__(192, 3) k_gi(
    const int* __restrict__ nbr_nid, const int* __restrict__ nbr_eid,
    const float* __restrict__ nbr_ts, const float* __restrict__ interact_t,
    const int* __restrict__ other_ids, const float* __restrict__ edge_raw,
    const float* __restrict__ W_edge, const float* __restrict__ W_struct,
    const float* __restrict__ W_time, const float* __restrict__ time_w,
    const float* __restrict__ time_b, const float* __restrict__ W_ih,
    const float* __restrict__ b_ih, const float* __restrict__ b_feat,
    const float* __restrict__ b_edge, const float* __restrict__ b_time,
    const float* __restrict__ b_struct, float* __restrict__ GI) {
    const int b = blockIdx.x, tid = threadIdx.x;
    const int base = b * NSEQ;

    __shared__ __align__(16) float sP[NSEQ][64];
    __shared__ __align__(16) float X[NSEQ][64];
    __shared__ __align__(16) float te[NSEQ][16];
    __shared__ int s_nid[NSEQ];
    __shared__ int s_sk[NSEQ];
    __shared__ float s_e0[NSEQ], s_ts[NSEQ];

    // Phase A1: raw gathers
    if (tid < 50) s_nid[tid] = nbr_nid[base + tid];
    else if (tid >= 64 && tid < 114) s_ts[tid - 64] = nbr_ts[base + tid - 64];
    else if (tid >= 128 && tid < 178)
        s_e0[tid - 128] = edge_raw[(size_t)nbr_eid[base + tid - 128] * 4];
    __syncthreads();

    // Phase A2: time encodings (800 cos) + node projections gather
    const float tq = interact_t[b];
    for (int i = tid; i < NSEQ * TD; i += 192) {
        int t = i >> 4, k = i & 15;
        te[t][k] = cos_acc(__fadd_rn(__fmul_rn(tq - s_ts[t], time_w[k]), time_b[k]));
    }
    if (HAS_NODE) {
        if (tid < 50) s_sk[tid] = (int)g_skill[s_nid[tid]];
        for (int i = tid; i < NSEQ * 64; i += 192) {
            int tt = i >> 6, j = i & 63;
            sP[tt][j] = g_P[(size_t)s_nid[tt] * 64 + j];
        }
    }
    const int other = other_ids[b];
    __syncthreads();

    // Phase B: X[t][j] for all (t, j) in parallel
    {
        const int j = tid & 63;
        const int t0 = tid >> 6;
        const float We_r = W_edge[j], Ws_r = W_struct[j];
        float C_r = b_edge[j] + b_time[j] + b_struct[j];
        if (HAS_NODE) C_r += b_feat[j] + b_struct[j];
        float Wt_r[16];
#pragma unroll
        for (int k = 0; k < 16; k++) Wt_r[k] = W_time[k * 64 + j];
        const int dsk = HAS_NODE ? (int)g_skill[other] : 0;
        for (int t = t0; t < NSEQ; t += 3) {
            float s = (s_nid[t] == other) ? 1.f : 0.f;
            if (HAS_NODE) s += (s_sk[t] == dsk) ? 1.f : 0.f;
            float x = C_r;
            x = fmaf(s, Ws_r, x);
            x = fmaf(s_e0[t], We_r, x);
            if (HAS_NODE) x += sP[t][j];
#pragma unroll
            for (int k = 0; k < 16; k++) x = fmaf(te[t][k], Wt_r[k], x);
            X[t][j] = x;
        }
    }

    // W_ih row -> packed regs (issued while phase B drains)
    u64 w2[32];
    {
        const float4* wp = (const float4*)(W_ih + (size_t)tid * 64);
#pragma unroll
        for (int j4 = 0; j4 < 16; j4++) {
            float4 v = wp[j4];
            w2[2 * j4] = pack2(v.x, v.y);
            w2[2 * j4 + 1] = pack2(v.z, v.w);
        }
    }
    const float bih = b_ih[tid];
    __syncthreads();

    // Phase C: 50 independent dots. 2 timesteps x 2 accumulators per iteration.
    const uint32_t xbase = (uint32_t)__cvta_generic_to_shared(X);
    float* gout = GI + (size_t)base * G3 + tid;
    for (int t = 0; t < NSEQ; t += 2) {
        const uint32_t x0 = xbase + (uint32_t)t * 256;
        const uint32_t x1 = x0 + 256;
        u64 a0 = 0ull, a1 = 0ull, b0 = 0ull, b1 = 0ull;
#pragma unroll
        for (int j = 0; j < 8; j++) {
            u64 p, q, r, s;
            lds_v2u64(x0 + j * 16, p, q);
            lds_v2u64(x1 + j * 16, r, s);
            a0 = ffma2(w2[2 * j], p, a0);
            a0 = ffma2(w2[2 * j + 1], q, a0);
            a1 = ffma2(w2[2 * j], r, a1);
            a1 = ffma2(w2[2 * j + 1], s, a1);
        }
#pragma unroll
        for (int j = 8; j < 16; j++) {
            u64 p, q, r, s;
            lds_v2u64(x0 + j * 16, p, q);
            lds_v2u64(x1 + j * 16, r, s);
            b0 = ffma2(w2[2 * j], p, b0);
            b0 = ffma2(w2[2 * j + 1], q, b0);
            b1 = ffma2(w2[2 * j], r, b1);
            b1 = ffma2(w2[2 * j + 1], s, b1);
        }
        float lo, hi, lo2, hi2;
        unpack2(a0, lo, hi); unpack2(b0, lo2, hi2);
        gout[(size_t)t * G3] = bih + (lo + hi) + (lo2 + hi2);
        unpack2(a1, lo, hi); unpack2(b1, lo2, hi2);
        gout[(size_t)(t + 1) * G3] = bih + (lo + hi) + (lo2 + hi2);
    }
}

// ---------------- K4/K5: GRU recurrence + tail + output linear ----------------
// 9 batch rows per block, 192 threads. Thread k owns W_hh row k (packed).
// gi loads for t+1 are prefetched during timestep t.
template <bool ADD_NODE>
__global__ void __launch_bounds__(192, 3) k_gru(
    const float* __restrict__ GI, const float* __restrict__ W_hh,
    const float* __restrict__ b_hh, const float* __restrict__ W_out,
    const float* __restrict__ b_out, const float* __restrict__ W_time,
    const float* __restrict__ time_b, const float* __restrict__ W_edge,
    const float* __restrict__ b_edge, const float* __restrict__ b_time,
    const float* __restrict__ edge_raw, const float* __restrict__ b_feat,
    const int* __restrict__ node_ids, float* __restrict__ outp) {
    const int tid = threadIdx.x;
    const int b0 = blockIdx.x * GRWS;
    const int rows = min(GRWS, BATCH - b0);

    __shared__ __align__(16) float h_sh[GRWS * 64];
    __shared__ __align__(16) float gh_sh[GRWS * G3];
    __shared__ float tail_sh[64];

    u64 w2[32];
    {
        const float4* wp = (const float4*)(W_hh + (size_t)tid * 64);
#pragma unroll
        for (int j4 = 0; j4 < 16; j4++) {
            float4 v = wp[j4];
            w2[2 * j4] = pack2(v.x, v.y);
            w2[2 * j4 + 1] = pack2(v.z, v.w);
        }
    }
    const float bhh = b_hh[tid];
    const uint32_t h_base = (uint32_t)__cvta_generic_to_shared(h_sh);

    for (int i = tid; i < GRWS * 64; i += 192) h_sh[i] = 0.f;
    if (tid < 64) {
        float tl = b_time[tid] + b_edge[tid] + edge_raw[0] * W_edge[tid];
        if (ADD_NODE) tl += b_feat[tid];
#pragma unroll
        for (int kk = 0; kk < 16; kk++)
            tl = fmaf(cos_acc(time_b[kk]), W_time[kk * 64 + tid], tl);
        tail_sh[tid] = tl;
    }

    const int r1 = tid >> 6, j1 = tid & 63;
    bool act[3];
    const float* gp[3];
    float gc[3][3], gn[3][3];
#pragma unroll
    for (int s = 0; s < 3; s++) {
        int r = r1 + 3 * s;
        act[s] = (r < rows);
        gp[s] = GI + ((size_t)(b0 + (act[s] ? r : 0)) * NSEQ) * G3 + j1;
#pragma unroll
        for (int g = 0; g < 3; g++) gc[s][g] = act[s] ? gp[s][g * 64] : 0.f;
    }
    __syncthreads();

    for (int t = 0; t < NSEQ; t++) {
        // gh[r][k] = b_hh[k] + dot(W_hh[k,:], h[r]) — 9 independent chains
#pragma unroll
        for (int r = 0; r < GRWS; r++) {
            if (r < rows) {
                u64 acc2 = 0ull;
                const uint32_t ha = h_base + (uint32_t)r * 256;
#pragma unroll
                for (int j = 0; j < 16; j++) {
                    u64 p, q;
                    lds_v2u64(ha + j * 16, p, q);
                    acc2 = ffma2(w2[2 * j], p, acc2);
                    acc2 = ffma2(w2[2 * j + 1], q, acc2);
                }
                float lo, hi; unpack2(acc2, lo, hi);
                gh_sh[r * G3 + tid] = bhh + lo + hi;
            }
        }
        // prefetch gi(t+1) — consumed next iteration, a full t of latency cover
        if (t + 1 < NSEQ) {
            const size_t off = (size_t)(t + 1) * G3;
#pragma unroll
            for (int s = 0; s < 3; s++)
                if (act[s]) {
                    gn[s][0] = gp[s][off];
                    gn[s][1] = gp[s][off + 64];
                    gn[s][2] = gp[s][off + 128];
                }
        }
        __syncthreads();
#pragma unroll
        for (int s = 0; s < 3; s++) {
            if (act[s]) {
                const int r = r1 + 3 * s;
                float rg = sigmoid_(gc[s][0] + gh_sh[r * G3 + j1]);
                float z = sigmoid_(gc[s][1] + gh_sh[r * G3 + 64 + j1]);
                float n = tanh_(fmaf(rg, gh_sh[r * G3 + 128 + j1], gc[s][2]));
                float hold = h_sh[r * 64 + j1];
                h_sh[r * 64 + j1] = (1.f - z) * n + z * hold;
            }
        }
        __syncthreads();
#pragma unroll
        for (int s = 0; s < 3; s++) {
#pragma unroll
            for (int g = 0; g < 3; g++) gc[s][g] = gn[s][g];
        }
    }

    // emb = h + tail (+ P[node] for dst) staged into gh_sh
#pragma unroll
    for (int s = 0; s < 3; s++) {
        if (act[s]) {
            const int r = r1 + 3 * s;
            float e = h_sh[r * 64 + j1] + tail_sh[j1];
            if (ADD_NODE) e += g_P[(size_t)node_ids[b0 + r] * 64 + j1];
            gh_sh[r * 64 + j1] = e;
        }
    }
    __syncthreads();

    // out = emb @ W_out + b_out
#pragma unroll
    for (int s = 0; s < 3; s++) {
        if (act[s]) {
            const int r = r1 + 3 * s;
            float acc = b_out[j1];
            const float* em = gh_sh + r * 64;
#pragma unroll 8
            for (int m = 0; m < 64; m++) acc = fmaf(em[m], W_out[m * 64 + j1], acc);
            outp[(size_t)(b0 + r) * 64 + j1] = acc;
        }
    }
}

// ---------------- launch ----------------
extern "C" void kernel_launch(void* const* d_in, const int* in_sizes, int n_in,
                              void* d_out, int out_size) {
    const float* node_raw = (const float*)d_in[0];
    const float* edge_raw = (const float*)d_in[1];
    const int* src_ids = (const int*)d_in[2];
    const int* dst_ids = (const int*)d_in[3];
    const float* t_int = (const float*)d_in[4];
    const int* s_nnid = (const int*)d_in[5];
    const int* s_neid = (const int*)d_in[6];
    const float* s_nts = (const float*)d_in[7];
    const int* d_nnid = (const int*)d_in[8];
    const int* d_neid = (const int*)d_in[9];
    const float* d_nts = (const float*)d_in[10];
    const float* W_feat = (const float*)d_in[11];
    const float* b_feat = (const float*)d_in[12];
    const float* W_edge = (const float*)d_in[13];
    const float* b_edge = (const float*)d_in[14];
    const float* W_time = (const float*)d_in[15];
    const float* b_time = (const float*)d_in[16];
    const float* W_struct = (const float*)d_in[17];
    const float* b_struct = (const float*)d_in[18];
    const float* W_out = (const float*)d_in[19];
    const float* b_out = (const float*)d_in[20];
    const float* time_w = (const float*)d_in[21];
    const float* time_b = (const float*)d_in[22];
    const float* sWih = (const float*)d_in[23];
    const float* sWhh = (const float*)d_in[24];
    const float* sbih = (const float*)d_in[25];
    const float* sbhh = (const float*)d_in[26];
    const float* dWih = (const float*)d_in[27];
    const float* dWhh = (const float*)d_in[28];
    const float* dbih = (const float*)d_in[29];
    const float* dbhh = (const float*)d_in[30];

    float* out = (float*)d_out;

    float* GIs_p; cudaGetSymbolAddress((void**)&GIs_p, g_GIs);
    float* GId_p; cudaGetSymbolAddress((void**)&GId_p, g_GId);

    // K1: node projection table
    k_nodeproj<<<NUM_NODES / 4, 256>>>(node_raw, W_feat);

    // K2: src gi (node feats + skill + co), other = dst node ids
    k_gi<true><<<BATCH, 192>>>(s_nnid, s_neid, s_nts, t_int, dst_ids, edge_raw,
                               W_edge, W_struct, W_time, time_w, time_b,
                               sWih, sbih, b_feat, b_edge, b_time, b_struct, GIs_p);
    // K3: dst gi (edge+time+co only), other = src node ids
    k_gi<false><<<BATCH, 192>>>(d_nnid, d_neid, d_nts, t_int, src_ids, edge_raw,
                                W_edge, W_struct, W_time, time_w, time_b,
                                dWih, dbih, b_feat, b_edge, b_time, b_struct, GId_p);

    const int gru_grid = (BATCH + GRWS - 1) / GRWS;
    // K4: src GRU -> out[0 : B*64]
    k_gru<false><<<gru_grid, 192>>>(GIs_p, sWhh, sbhh, W_out, b_out, W_time,
                                    time_b, W_edge, b_edge, b_time, edge_raw,
                                    b_feat, nullptr, out);
    // K5: dst GRU (+ P[dst]+b_feat) -> out[B*64 : 2*B*64]
    k_gru<true><<<gru_grid, 192>>>(GId_p, dWhh, dbhh, W_out, b_out, W_time,
                                   time_b, W_edge, b_edge, b_time, edge_raw,
                                   b_feat, dst_ids, out + (size_t)BATCH * 64);
}

// round 5
// speedup vs baseline: 1.2224x; 1.1188x over previous
#include <cuda_runtime.h>
#include <cuda_bf16.h>
#include <cstddef>
#include <cstdint>

#define BATCH 8192
#define NSEQ 50
#define NUM_NODES 200000
#define FEAT 64
#define TD 16
#define DH 64
#define G3 192
#define GRWS 6          // batch rows per k_gru block
#define TCHUNK 10       // timesteps per k_gi phase-C chunk

typedef unsigned long long u64;

// ---------------- static device scratch ----------------
__device__ float g_P[(size_t)NUM_NODES * FEAT];
__device__ float g_skill[NUM_NODES];
__device__ float g_GIs[(size_t)BATCH * NSEQ * G3];
__device__ float g_GId[(size_t)BATCH * NSEQ * G3];

// ---------------- packed f32x2 helpers ----------------
__device__ __forceinline__ u64 pack2(float lo, float hi) {
    u64 d; asm("mov.b64 %0, {%1, %2};" : "=l"(d) : "f"(lo), "f"(hi)); return d;
}
__device__ __forceinline__ void unpack2(u64 v, float& lo, float& hi) {
    asm("mov.b64 {%0, %1}, %2;" : "=f"(lo), "=f"(hi) : "l"(v));
}
__device__ __forceinline__ u64 ffma2(u64 a, u64 b, u64 c) {
    u64 d; asm("fma.rn.f32x2 %0, %1, %2, %3;" : "=l"(d) : "l"(a), "l"(b), "l"(c));
    return d;
}
__device__ __forceinline__ void lds_v2u64(uint32_t addr, u64& a, u64& b) {
    asm volatile("ld.shared.v2.b64 {%0, %1}, [%2];" : "=l"(a), "=l"(b) : "r"(addr));
}

// ---------------- math helpers ----------------
__device__ __forceinline__ float cos_acc(float x) {
    const double TP = 6.283185307179586476925287;
    const float C1 = 6.28125f;
    const float C2 = (float)(TP - (double)C1);
    const float C3 = (float)(TP - (double)C1 - (double)((float)(TP - (double)C1)));
    const float INV2PI = 0.15915494309189535f;
    float k = rintf(x * INV2PI);
    float r = fmaf(-k, C1, x);
    r = fmaf(-k, C2, r);
    r = fmaf(-k, C3, r);
    return __cosf(r);
}
__device__ __forceinline__ float sigmoid_(float x) { return 1.0f / (1.0f + __expf(-x)); }
__device__ __forceinline__ float tanh_(float x) {
    float e = __expf(2.0f * x);
    return (e - 1.0f) / (e + 1.0f);
}

// ---------------- K1: node projection table ----------------
__global__ void __launch_bounds__(256) k_nodeproj(const float* __restrict__ nodef,
                                                  const float* __restrict__ Wf) {
    __shared__ float Wsm[4096];
    __shared__ __align__(16) float rowb[4][64];
    const int tid = threadIdx.x;
    for (int i = tid; i < 4096; i += 256) Wsm[i] = Wf[i];
    const int g = tid >> 6, j = tid & 63;
    const int n = blockIdx.x * 4 + g;
    rowb[g][j] = nodef[(size_t)n * 64 + j];
    __syncthreads();
    float acc = 0.f;
#pragma unroll
    for (int k = 0; k < 64; k++) acc = fmaf(rowb[g][k], Wsm[k * 64 + j], acc);
    g_P[(size_t)n * 64 + j] = acc;
    if (j == 0) g_skill[n] = rowb[g][0];
}

// ---------------- K2/K3: gi precompute, 384 threads, split-K phase C ----------------
template <bool HAS_NODE>
__global__ void __launch_bounds__(384, 3) k_gi(
    const int* __restrict__ nbr_nid, const int* __restrict__ nbr_eid,
    const float* __restrict__ nbr_ts, const float* __restrict__ interact_t,
    const int* __restrict__ other_ids, const float* __restrict__ edge_raw,
    const float* __restrict__ W_edge, const float* __restrict__ W_struct,
    const float* __restrict__ W_time, const float* __restrict__ time_w,
    const float* __restrict__ time_b, const float* __restrict__ W_ih,
    const float* __restrict__ b_ih, const float* __restrict__ b_feat,
    const float* __restrict__ b_edge, const float* __restrict__ b_time,
    const float* __restrict__ b_struct, float* __restrict__ GI) {
    const int b = blockIdx.x, tid = threadIdx.x;
    const int base = b * NSEQ;

    __shared__ __align__(16) float sP[NSEQ][64];
    __shared__ __align__(16) float X[NSEQ][64];
    __shared__ __align__(16) float te[NSEQ][16];
    __shared__ float psum[2][TCHUNK * G3];
    __shared__ float s_bih[G3];
    __shared__ int s_nid[NSEQ], s_sk[NSEQ];
    __shared__ float s_e0[NSEQ], s_ts[NSEQ];

    // Phase A1: raw gathers
    if (tid < 50) s_nid[tid] = nbr_nid[base + tid];
    else if (tid >= 64 && tid < 114) s_ts[tid - 64] = nbr_ts[base + tid - 64];
    else if (tid >= 128 && tid < 178)
        s_e0[tid - 128] = edge_raw[(size_t)nbr_eid[base + tid - 128] * 4];
    if (tid >= 192 && tid < 384) s_bih[tid - 192] = b_ih[tid - 192];
    __syncthreads();

    // Phase A2: time encodings + node projection gather
    const float tq = interact_t[b];
    for (int i = tid; i < NSEQ * TD; i += 384) {
        int t = i >> 4, k = i & 15;
        te[t][k] = cos_acc(__fadd_rn(__fmul_rn(tq - s_ts[t], time_w[k]), time_b[k]));
    }
    if (HAS_NODE) {
        if (tid < 50) s_sk[tid] = (int)g_skill[s_nid[tid]];
        for (int i = tid; i < NSEQ * 64; i += 384) {
            int tt = i >> 6, j = i & 63;
            sP[tt][j] = g_P[(size_t)s_nid[tt] * 64 + j];
        }
    }
    const int other = other_ids[b];
    __syncthreads();

    // Phase B: X[t][j], 6 timesteps per pass
    {
        const int j = tid & 63;
        const int t0 = tid >> 6;   // 0..5
        const float We_r = W_edge[j], Ws_r = W_struct[j];
        float C_r = b_edge[j] + b_time[j] + b_struct[j];
        if (HAS_NODE) C_r += b_feat[j] + b_struct[j];
        float Wt_r[16];
#pragma unroll
        for (int k = 0; k < 16; k++) Wt_r[k] = W_time[k * 64 + j];
        const int dsk = HAS_NODE ? (int)g_skill[other] : 0;
        for (int t = t0; t < NSEQ; t += 6) {
            float s = (s_nid[t] == other) ? 1.f : 0.f;
            if (HAS_NODE) s += (s_sk[t] == dsk) ? 1.f : 0.f;
            float x = C_r;
            x = fmaf(s, Ws_r, x);
            x = fmaf(s_e0[t], We_r, x);
            if (HAS_NODE) x += sP[t][j];
#pragma unroll
            for (int k = 0; k < 16; k++) x = fmaf(te[t][k], Wt_r[k], x);
            X[t][j] = x;
        }
    }

    // split-K assignment: thread = (k, half); owns half a W_ih row (16 u64)
    const int k = tid % G3;
    const int half = tid / G3;
    u64 w2[16];
    {
        const float4* wp = (const float4*)(W_ih + (size_t)k * 64 + half * 32);
#pragma unroll
        for (int j4 = 0; j4 < 8; j4++) {
            float4 v = wp[j4];
            w2[2 * j4] = pack2(v.x, v.y);
            w2[2 * j4 + 1] = pack2(v.z, v.w);
        }
    }
    const uint32_t xbase = (uint32_t)__cvta_generic_to_shared(X) + (uint32_t)half * 128;
    float* myp = psum[half];
    __syncthreads();

    // Phase C: chunks of TCHUNK timesteps; half-dots -> psum; combine -> GI
    for (int c = 0; c < NSEQ / TCHUNK; c++) {
        const int tb = c * TCHUNK;
#pragma unroll
        for (int i = 0; i < TCHUNK; i++) {
            const uint32_t xa = xbase + (uint32_t)(tb + i) * 256;
            u64 a0 = 0ull, a1 = 0ull;
#pragma unroll
            for (int j = 0; j < 8; j++) {
                u64 p, q;
                lds_v2u64(xa + j * 16, p, q);
                a0 = ffma2(w2[2 * j], p, a0);
                a1 = ffma2(w2[2 * j + 1], q, a1);
            }
            float lo, hi, lo2, hi2;
            unpack2(a0, lo, hi); unpack2(a1, lo2, hi2);
            myp[i * G3 + k] = (lo + hi) + (lo2 + hi2);
        }
        __syncthreads();
        // combine: coalesced GI writes
        float* gdst = GI + ((size_t)(base + tb)) * G3;
#pragma unroll
        for (int e = 0; e < TCHUNK * G3 / 384; e++) {
            int idx = e * 384 + tid;
            gdst[idx] = psum[0][idx] + psum[1][idx] + s_bih[idx % G3];
        }
        __syncthreads();
    }
}

// ---------------- K4/K5: GRU, 384 threads, split-K gh ----------------
template <bool ADD_NODE>
__global__ void __launch_bounds__(384, 3) k_gru(
    const float* __restrict__ GI, const float* __restrict__ W_hh,
    const float* __restrict__ b_hh, const float* __restrict__ W_out,
    const float* __restrict__ b_out, const float* __restrict__ W_time,
    const float* __restrict__ time_b, const float* __restrict__ W_edge,
    const float* __restrict__ b_edge, const float* __restrict__ b_time,
    const float* __restrict__ edge_raw, const float* __restrict__ b_feat,
    const int* __restrict__ node_ids, float* __restrict__ outp) {
    const int tid = threadIdx.x;
    const int b0 = blockIdx.x * GRWS;
    const int rows = min(GRWS, BATCH - b0);

    __shared__ __align__(16) float h_sh[GRWS * 64];
    __shared__ float psA[GRWS * G3];
    __shared__ float psB[GRWS * G3];
    __shared__ float tail_sh[64];

    // phase-1 role: (k, half) owns half of W_hh row k
    const int k = tid % G3;
    const int half = tid / G3;
    u64 w2[16];
    {
        const float4* wp = (const float4*)(W_hh + (size_t)k * 64 + half * 32);
#pragma unroll
        for (int j4 = 0; j4 < 8; j4++) {
            float4 v = wp[j4];
            w2[2 * j4] = pack2(v.x, v.y);
            w2[2 * j4 + 1] = pack2(v.z, v.w);
        }
    }
    const float bhh = half ? 0.f : b_hh[k];
    float* myp = half ? psB : psA;
    const uint32_t h_base = (uint32_t)__cvta_generic_to_shared(h_sh) + (uint32_t)half * 128;

    for (int i = tid; i < GRWS * 64; i += 384) h_sh[i] = 0.f;
    if (tid < 64) {
        float tl = b_time[tid] + b_edge[tid] + edge_raw[0] * W_edge[tid];
        if (ADD_NODE) tl += b_feat[tid];
#pragma unroll
        for (int kk = 0; kk < 16; kk++)
            tl = fmaf(cos_acc(time_b[kk]), W_time[kk * 64 + tid], tl);
        tail_sh[tid] = tl;
    }

    // phase-2 role: (r2, j2) — 384 = 6 x 64 exactly
    const int r2 = tid >> 6, j2 = tid & 63;
    const bool act2 = (r2 < rows);
    const float* gp = GI + ((size_t)(b0 + (act2 ? r2 : 0)) * NSEQ) * G3 + j2;
    float gc0 = 0.f, gc1 = 0.f, gc2 = 0.f;
    if (act2) { gc0 = gp[0]; gc1 = gp[64]; gc2 = gp[128]; }
    __syncthreads();

    for (int t = 0; t < NSEQ; t++) {
        // phase 1: half-dots for all rows
#pragma unroll
        for (int r = 0; r < GRWS; r++) {
            if (r < rows) {
                const uint32_t ha = h_base + (uint32_t)r * 256;
                u64 a0 = 0ull, a1 = 0ull;
#pragma unroll
                for (int j = 0; j < 8; j++) {
                    u64 p, q;
                    lds_v2u64(ha + j * 16, p, q);
                    a0 = ffma2(w2[2 * j], p, a0);
                    a1 = ffma2(w2[2 * j + 1], q, a1);
                }
                float lo, hi, lo2, hi2;
                unpack2(a0, lo, hi); unpack2(a1, lo2, hi2);
                myp[r * G3 + k] = bhh + (lo + hi) + (lo2 + hi2);
            }
        }
        // prefetch gi(t+1) in phase-2 mapping
        float gn0 = 0.f, gn1 = 0.f, gn2 = 0.f;
        if (act2 && t + 1 < NSEQ) {
            const size_t off = (size_t)(t + 1) * G3;
            gn0 = gp[off]; gn1 = gp[off + 64]; gn2 = gp[off + 128];
        }
        __syncthreads();
        // phase 2: gates + h update
        if (act2) {
            float ghr = psA[r2 * G3 + j2] + psB[r2 * G3 + j2];
            float ghz = psA[r2 * G3 + 64 + j2] + psB[r2 * G3 + 64 + j2];
            float ghn = psA[r2 * G3 + 128 + j2] + psB[r2 * G3 + 128 + j2];
            float rg = sigmoid_(gc0 + ghr);
            float z = sigmoid_(gc1 + ghz);
            float n = tanh_(fmaf(rg, ghn, gc2));
            float hold = h_sh[r2 * 64 + j2];
            h_sh[r2 * 64 + j2] = (1.f - z) * n + z * hold;
        }
        __syncthreads();
        gc0 = gn0; gc1 = gn1; gc2 = gn2;
    }

    // epilogue: emb = h + tail (+P[node]); out = emb @ W_out + b_out
    if (act2) {
        float e = h_sh[r2 * 64 + j2] + tail_sh[j2];
        if (ADD_NODE) e += g_P[(size_t)node_ids[b0 + r2] * 64 + j2];
        psA[r2 * 64 + j2] = e;
    }
    __syncthreads();
    if (act2) {
        float acc = b_out[j2];
        const float* em = psA + r2 * 64;
#pragma unroll 8
        for (int m = 0; m < 64; m++) acc = fmaf(em[m], W_out[m * 64 + j2], acc);
        outp[(size_t)(b0 + r2) * 64 + j2] = acc;
    }
}

// ---------------- launch ----------------
extern "C" void kernel_launch(void* const* d_in, const int* in_sizes, int n_in,
                              void* d_out, int out_size) {
    const float* node_raw = (const float*)d_in[0];
    const float* edge_raw = (const float*)d_in[1];
    const int* src_ids = (const int*)d_in[2];
    const int* dst_ids = (const int*)d_in[3];
    const float* t_int = (const float*)d_in[4];
    const int* s_nnid = (const int*)d_in[5];
    const int* s_neid = (const int*)d_in[6];
    const float* s_nts = (const float*)d_in[7];
    const int* d_nnid = (const int*)d_in[8];
    const int* d_neid = (const int*)d_in[9];
    const float* d_nts = (const float*)d_in[10];
    const float* W_feat = (const float*)d_in[11];
    const float* b_feat = (const float*)d_in[12];
    const float* W_edge = (const float*)d_in[13];
    const float* b_edge = (const float*)d_in[14];
    const float* W_time = (const float*)d_in[15];
    const float* b_time = (const float*)d_in[16];
    const float* W_struct = (const float*)d_in[17];
    const float* b_struct = (const float*)d_in[18];
    const float* W_out = (const float*)d_in[19];
    const float* b_out = (const float*)d_in[20];
    const float* time_w = (const float*)d_in[21];
    const float* time_b = (const float*)d_in[22];
    const float* sWih = (const float*)d_in[23];
    const float* sWhh = (const float*)d_in[24];
    const float* sbih = (const float*)d_in[25];
    const float* sbhh = (const float*)d_in[26];
    const float* dWih = (const float*)d_in[27];
    const float* dWhh = (const float*)d_in[28];
    const float* dbih = (const float*)d_in[29];
    const float* dbhh = (const float*)d_in[30];

    float* out = (float*)d_out;

    float* GIs_p; cudaGetSymbolAddress((void**)&GIs_p, g_GIs);
    float* GId_p; cudaGetSymbolAddress((void**)&GId_p, g_GId);

    k_nodeproj<<<NUM_NODES / 4, 256>>>(node_raw, W_feat);

    k_gi<true><<<BATCH, 384>>>(s_nnid, s_neid, s_nts, t_int, dst_ids, edge_raw,
                               W_edge, W_struct, W_time, time_w, time_b,
                               sWih, sbih, b_feat, b_edge, b_time, b_struct, GIs_p);
    k_gi<false><<<BATCH, 384>>>(d_nnid, d_neid, d_nts, t_int, src_ids, edge_raw,
                                W_edge, W_struct, W_time, time_w, time_b,
                                dWih, dbih, b_feat, b_edge, b_time, b_struct, GId_p);

    const int gru_grid = (BATCH + GRWS - 1) / GRWS;
    k_gru<false><<<gru_grid, 384>>>(GIs_p, sWhh, sbhh, W_out, b_out, W_time,
                                    time_b, W_edge, b_edge, b_time, edge_raw,
                                    b_feat, nullptr, out);
    k_gru<true><<<gru_grid, 384>>>(GId_p, dWhh, dbhh, W_out, b_out, W_time,
                                   time_b, W_edge, b_edge, b_time, edge_raw,
                                   b_feat, dst_ids, out + (size_t)BATCH * 64);
}

// round 6
// speedup vs baseline: 1.2385x; 1.0132x over previous
#include <cuda_runtime.h>
#include <cstddef>
#include <cstdint>

#define BATCH 8192
#define NSEQ 50
#define NUM_NODES 200000
#define TD 16
#define DH 64
#define G3 192
#define RW 6           // batch rows per fused block
#define TC 5           // timesteps per chunk
#define THR 384

typedef unsigned long long u64;

// ---------------- static device scratch ----------------
__device__ float g_P[(size_t)NUM_NODES * DH];
__device__ float g_skill[NUM_NODES];
__device__ u64 g_Wps[2 * 16 * G3];   // permuted packed W_ih (src): [half*16+kk][k]
__device__ u64 g_Wpd[2 * 16 * G3];   // permuted packed W_ih (dst)

// ---------------- packed f32x2 helpers ----------------
__device__ __forceinline__ u64 pack2(float lo, float hi) {
    u64 d; asm("mov.b64 %0, {%1, %2};" : "=l"(d) : "f"(lo), "f"(hi)); return d;
}
__device__ __forceinline__ void unpack2(u64 v, float& lo, float& hi) {
    asm("mov.b64 {%0, %1}, %2;" : "=f"(lo), "=f"(hi) : "l"(v));
}
__device__ __forceinline__ u64 ffma2(u64 a, u64 b, u64 c) {
    u64 d; asm("fma.rn.f32x2 %0, %1, %2, %3;" : "=l"(d) : "l"(a), "l"(b), "l"(c));
    return d;
}
__device__ __forceinline__ void lds_v2u64(uint32_t addr, u64& a, u64& b) {
    asm volatile("ld.shared.v2.b64 {%0, %1}, [%2];" : "=l"(a), "=l"(b) : "r"(addr));
}
__device__ __forceinline__ uint32_t smem_u32(const void* p) {
    return (uint32_t)__cvta_generic_to_shared(p);
}

// ---------------- math helpers ----------------
__device__ __forceinline__ float cos_acc(float x) {
    const double TP = 6.283185307179586476925287;
    const float C1 = 6.28125f;
    const float C2 = (float)(TP - (double)C1);
    const float C3 = (float)(TP - (double)C1 - (double)((float)(TP - (double)C1)));
    const float INV2PI = 0.15915494309189535f;
    float k = rintf(x * INV2PI);
    float r = fmaf(-k, C1, x);
    r = fmaf(-k, C2, r);
    r = fmaf(-k, C3, r);
    return __cosf(r);
}
__device__ __forceinline__ float sigmoid_(float x) { return 1.0f / (1.0f + __expf(-x)); }
__device__ __forceinline__ float tanh_(float x) {
    float e = __expf(2.0f * x);
    return (e - 1.0f) / (e + 1.0f);
}

// ---------------- K1: node projection table ----------------
__global__ void __launch_bounds__(256) k_nodeproj(const float* __restrict__ nodef,
                                                  const float* __restrict__ Wf) {
    __shared__ float Wsm[4096];
    __shared__ __align__(16) float rowb[4][64];
    const int tid = threadIdx.x;
    for (int i = tid; i < 4096; i += 256) Wsm[i] = Wf[i];
    const int g = tid >> 6, j = tid & 63;
    const int n = blockIdx.x * 4 + g;
    rowb[g][j] = nodef[(size_t)n * 64 + j];
    __syncthreads();
    float acc = 0.f;
#pragma unroll
    for (int k = 0; k < 64; k++) acc = fmaf(rowb[g][k], Wsm[k * 64 + j], acc);
    g_P[(size_t)n * 64 + j] = acc;
    if (j == 0) g_skill[n] = rowb[g][0];
}

// ---------------- K2: permute+pack W_ih for both sides ----------------
__global__ void k_prep(const float* __restrict__ sWih, const float* __restrict__ dWih) {
    int i = blockIdx.x * 256 + threadIdx.x;
    if (i < 32 * G3) {
        int k = i % G3, q = i / G3;       // q = half*16 + kk
        int half = q >> 4, kk = q & 15;
        int col = half * 32 + 2 * kk;
        g_Wps[i] = pack2(sWih[(size_t)k * 64 + col], sWih[(size_t)k * 64 + col + 1]);
        g_Wpd[i] = pack2(dWih[(size_t)k * 64 + col], dWih[(size_t)k * 64 + col + 1]);
    }
}

// ---------------- fused gi + GRU kernel ----------------
struct SM {
    float giH[2][TC][RW][G3];   // 46080 B : gi split-K halves for chunk
    float ghH[2][RW][G3];       //  9216 B : gh split-K halves for one t
    float X[TC][RW][DH];        //  7680 B
    float te[TC][RW][TD];       //  1920 B
    u64   Wt2[8][DH];           //  4096 B : W_time packed pairs [kk][j]
    float h[RW][DH];            //  1536 B
    int   nid[RW][NSEQ];        //  1200 B
    int   sk[RW][NSEQ];         //  1200 B
    float e0[RW][NSEQ];         //  1200 B
    float dt[RW][NSEQ];         //  1200 B
    float Csm[DH], Wesm[DH], Wssm[DH], tailv[DH];   // 1024 B
    float tw[TD], tb[TD];       //   128 B
    int   other[RW];
    int   dsk[RW];
};

template <bool HAS_NODE>
__global__ void __launch_bounds__(THR, 2) k_fused(
    const int* __restrict__ nbr_nid, const int* __restrict__ nbr_eid,
    const float* __restrict__ nbr_ts, const float* __restrict__ t_int,
    const int* __restrict__ other_ids, const int* __restrict__ epi_ids,
    const float* __restrict__ edge_raw,
    const float* __restrict__ W_edge, const float* __restrict__ W_struct,
    const float* __restrict__ W_time, const float* __restrict__ time_w,
    const float* __restrict__ time_b,
    const u64* __restrict__ Wihp, const float* __restrict__ b_ih,
    const float* __restrict__ W_hh, const float* __restrict__ b_hh,
    const float* __restrict__ b_feat, const float* __restrict__ b_edge,
    const float* __restrict__ b_time, const float* __restrict__ b_struct,
    const float* __restrict__ W_out, const float* __restrict__ b_out,
    float* __restrict__ outp)
{
    extern __shared__ char smraw[];
    SM* s = (SM*)smraw;
    const int tid = threadIdx.x;
    const int b0 = blockIdx.x * RW;
    const int rows = min(RW, BATCH - b0);

    // role A: split-K over the 192 outputs
    const int half = (tid >= G3) ? 1 : 0;
    const int k = tid - half * G3;
    // role B: (row, feature)
    const int j = tid & 63, rg = tid >> 6;

    // ---- init ----
    if (tid < RW) {
        bool ok = tid < rows;
        int o = ok ? other_ids[b0 + tid] : 0;
        s->other[tid] = ok ? o : -1;
        if (HAS_NODE) s->dsk[tid] = (int)g_skill[o];
    }
    for (int i = tid; i < RW * NSEQ; i += THR) {
        int r = i / NSEQ, t = i - r * NSEQ;
        int gr = b0 + r;
        bool ok = r < rows;
        int gidx = ok ? gr * NSEQ + t : t;
        int nd = nbr_nid[gidx];
        ((int*)s->nid)[i] = nd;
        ((float*)s->dt)[i] = ok ? (t_int[gr] - nbr_ts[gidx]) : 0.f;
        ((float*)s->e0)[i] = edge_raw[(size_t)nbr_eid[gidx] * 4];
        if (HAS_NODE) ((int*)s->sk)[i] = (int)g_skill[nd];
    }
    if (tid < DH) {
        float C = b_edge[tid] + b_time[tid] + b_struct[tid];
        if (HAS_NODE) C += b_feat[tid] + b_struct[tid];
        s->Csm[tid] = C;
        s->Wesm[tid] = W_edge[tid];
        s->Wssm[tid] = W_struct[tid];
        float tl = b_time[tid] + b_edge[tid] + edge_raw[0] * W_edge[tid];
        if (!HAS_NODE) tl += b_feat[tid];
#pragma unroll
        for (int kk = 0; kk < TD; kk++)
            tl = fmaf(cos_acc(time_b[kk]), W_time[kk * 64 + tid], tl);
        s->tailv[tid] = tl;
    } else if (tid < DH + TD) {
        s->tw[tid - DH] = time_w[tid - DH];
        s->tb[tid - DH] = time_b[tid - DH];
    }
    for (int i = tid; i < 8 * DH; i += THR) {
        int kk = i >> 6, jj = i & 63;
        s->Wt2[kk][jj] = pack2(W_time[(2 * kk) * 64 + jj], W_time[(2 * kk + 1) * 64 + jj]);
    }
    for (int i = tid; i < RW * DH; i += THR) ((float*)s->h)[i] = 0.f;

    // persistent: W_hh half-row in regs
    u64 w2[16];
    {
        const float4* wp = (const float4*)(W_hh + (size_t)k * 64 + half * 32);
#pragma unroll
        for (int q = 0; q < 8; q++) {
            float4 v = wp[q];
            w2[2 * q] = pack2(v.x, v.y);
            w2[2 * q + 1] = pack2(v.z, v.w);
        }
    }
    const float bhh = half ? 0.f : b_hh[k];
    const float bih = half ? 0.f : b_ih[k];
    const uint32_t Xb = smem_u32(s->X);
    const uint32_t hb = smem_u32(s->h);
    __syncthreads();

    for (int c = 0; c < NSEQ / TC; c++) {
        const int tb = c * TC;
        // (1) time encodings for the chunk: TC*RW*TD = 480 cos
        for (int i = tid; i < TC * RW * TD; i += THR) {
            int k16 = i & 15, p = i >> 4;
            int rr = p % RW, ii = p / RW;
            float d = s->dt[rr][tb + ii];
            ((float*)s->te)[i] =
                cos_acc(__fadd_rn(__fmul_rn(d, s->tw[k16]), s->tb[k16]));
        }
        __syncthreads();
        // (2) X build (role B)
        {
            const float Ws_ = s->Wssm[j], We_ = s->Wesm[j], C_ = s->Csm[j];
#pragma unroll
            for (int ii = 0; ii < TC; ii++) {
                int t = tb + ii;
                float sf = (s->nid[rg][t] == s->other[rg]) ? 1.f : 0.f;
                if (HAS_NODE) sf += (s->sk[rg][t] == s->dsk[rg]) ? 1.f : 0.f;
                float x = fmaf(sf, Ws_, C_);
                x = fmaf(s->e0[rg][t], We_, x);
                if (HAS_NODE) x += g_P[(size_t)s->nid[rg][t] * 64 + j];
                u64 acc2 = 0ull;
                const u64* tep = (const u64*)s->te[ii][rg];
#pragma unroll
                for (int kk = 0; kk < 8; kk++) acc2 = ffma2(s->Wt2[kk][j], tep[kk], acc2);
                float lo, hi; unpack2(acc2, lo, hi);
                s->X[ii][rg][j] = x + lo + hi;
            }
        }
        __syncthreads();
        // (3) gi half-dots for the whole chunk (role A), W_ih streamed coalesced
        {
            u64 wi[16];
            const u64* wp = Wihp + (size_t)half * 16 * G3 + k;
#pragma unroll
            for (int q = 0; q < 16; q++) wi[q] = wp[q * G3];
            const uint32_t xb0 = Xb + half * 128;
            float* gdst = &s->giH[half][0][0][k];
            for (int p = 0; p < TC * RW; p += 2) {
                uint32_t xa = xb0 + p * 256;
                u64 a0 = 0ull, a1 = 0ull, c0 = 0ull, c1 = 0ull;
#pragma unroll
                for (int q = 0; q < 8; q++) {
                    u64 pA, qA, pB, qB;
                    lds_v2u64(xa + q * 16, pA, qA);
                    lds_v2u64(xa + 256 + q * 16, pB, qB);
                    a0 = ffma2(wi[2 * q], pA, a0);
                    a1 = ffma2(wi[2 * q + 1], qA, a1);
                    c0 = ffma2(wi[2 * q], pB, c0);
                    c1 = ffma2(wi[2 * q + 1], qB, c1);
                }
                float l0, h0, l1, h1;
                unpack2(a0, l0, h0); unpack2(a1, l1, h1);
                gdst[p * G3] = bih + (l0 + h0) + (l1 + h1);
                unpack2(c0, l0, h0); unpack2(c1, l1, h1);
                gdst[(p + 1) * G3] = bih + (l0 + h0) + (l1 + h1);
            }
        }
        __syncthreads();
        // (4) recurrence, TC steps
        for (int ii = 0; ii < TC; ii++) {
            // phase 1: gh half-dots (role A)
#pragma unroll
            for (int r = 0; r < RW; r++) {
                if (r < rows) {
                    uint32_t ha = hb + r * 256 + half * 128;
                    u64 a0 = 0ull, a1 = 0ull;
#pragma unroll
                    for (int q = 0; q < 8; q++) {
                        u64 p_, q_;
                        lds_v2u64(ha + q * 16, p_, q_);
                        a0 = ffma2(w2[2 * q], p_, a0);
                        a1 = ffma2(w2[2 * q + 1], q_, a1);
                    }
                    float lo, hi, lo2, hi2;
                    unpack2(a0, lo, hi); unpack2(a1, lo2, hi2);
                    s->ghH[half][r][k] = bhh + (lo + hi) + (lo2 + hi2);
                }
            }
            __syncthreads();
            // phase 2: gates + h update (role B)
            if (rg < rows) {
                float gir = s->giH[0][ii][rg][j] + s->giH[1][ii][rg][j];
                float giz = s->giH[0][ii][rg][64 + j] + s->giH[1][ii][rg][64 + j];
                float gin = s->giH[0][ii][rg][128 + j] + s->giH[1][ii][rg][128 + j];
                float ghr = s->ghH[0][rg][j] + s->ghH[1][rg][j];
                float ghz = s->ghH[0][rg][64 + j] + s->ghH[1][rg][64 + j];
                float ghn = s->ghH[0][rg][128 + j] + s->ghH[1][rg][128 + j];
                float r_ = sigmoid_(gir + ghr);
                float z_ = sigmoid_(giz + ghz);
                float n_ = tanh_(fmaf(r_, ghn, gin));
                float ho = s->h[rg][j];
                s->h[rg][j] = (1.f - z_) * n_ + z_ * ho;
            }
            __syncthreads();
        }
    }

    // ---- epilogue: emb = h + tail (+ P[epi] for dst); out = emb @ W_out + b_out
    if (rg < rows) {
        float e = s->h[rg][j] + s->tailv[j];
        if (!HAS_NODE) e += g_P[(size_t)epi_ids[b0 + rg] * 64 + j];
        s->X[0][rg][j] = e;
    }
    __syncthreads();
    if (rg < rows) {
        float acc = b_out[j];
        const float* em = s->X[0][rg];
#pragma unroll 8
        for (int m = 0; m < 64; m++) acc = fmaf(em[m], W_out[m * 64 + j], acc);
        outp[(size_t)(b0 + rg) * 64 + j] = acc;
    }
}

// ---------------- launch ----------------
extern "C" void kernel_launch(void* const* d_in, const int* in_sizes, int n_in,
                              void* d_out, int out_size) {
    const float* node_raw = (const float*)d_in[0];
    const float* edge_raw = (const float*)d_in[1];
    const int* src_ids = (const int*)d_in[2];
    const int* dst_ids = (const int*)d_in[3];
    const float* t_int = (const float*)d_in[4];
    const int* s_nnid = (const int*)d_in[5];
    const int* s_neid = (const int*)d_in[6];
    const float* s_nts = (const float*)d_in[7];
    const int* d_nnid = (const int*)d_in[8];
    const int* d_neid = (const int*)d_in[9];
    const float* d_nts = (const float*)d_in[10];
    const float* W_feat = (const float*)d_in[11];
    const float* b_feat = (const float*)d_in[12];
    const float* W_edge = (const float*)d_in[13];
    const float* b_edge = (const float*)d_in[14];
    const float* W_time = (const float*)d_in[15];
    const float* b_time = (const float*)d_in[16];
    const float* W_struct = (const float*)d_in[17];
    const float* b_struct = (const float*)d_in[18];
    const float* W_out = (const float*)d_in[19];
    const float* b_out = (const float*)d_in[20];
    const float* time_w = (const float*)d_in[21];
    const float* time_b = (const float*)d_in[22];
    const float* sWih = (const float*)d_in[23];
    const float* sWhh = (const float*)d_in[24];
    const float* sbih = (const float*)d_in[25];
    const float* sbhh = (const float*)d_in[26];
    const float* dWih = (const float*)d_in[27];
    const float* dWhh = (const float*)d_in[28];
    const float* dbih = (const float*)d_in[29];
    const float* dbhh = (const float*)d_in[30];

    float* out = (float*)d_out;

    u64* Wps_p; cudaGetSymbolAddress((void**)&Wps_p, g_Wps);
    u64* Wpd_p; cudaGetSymbolAddress((void**)&Wpd_p, g_Wpd);

    const int smem = (int)sizeof(SM);
    cudaFuncSetAttribute(k_fused<true>, cudaFuncAttributeMaxDynamicSharedMemorySize, smem);
    cudaFuncSetAttribute(k_fused<false>, cudaFuncAttributeMaxDynamicSharedMemorySize, smem);

    k_nodeproj<<<NUM_NODES / 4, 256>>>(node_raw, W_feat);
    k_prep<<<(32 * G3 + 255) / 256, 256>>>(sWih, dWih);

    const int grid = (BATCH + RW - 1) / RW;
    // src side: node feats + skill in X; epilogue adds tail only
    k_fused<true><<<grid, THR, smem>>>(
        s_nnid, s_neid, s_nts, t_int, dst_ids, dst_ids, edge_raw,
        W_edge, W_struct, W_time, time_w, time_b,
        Wps_p, sbih, sWhh, sbhh,
        b_feat, b_edge, b_time, b_struct, W_out, b_out, out);
    // dst side: edge+time+co in X; epilogue adds b_feat + P[dst]
    k_fused<false><<<grid, THR, smem>>>(
        d_nnid, d_neid, d_nts, t_int, src_ids, dst_ids, edge_raw,
        W_edge, W_struct, W_time, time_w, time_b,
        Wpd_p, dbih, dWhh, dbhh,
        b_feat, b_edge, b_time, b_struct, W_out, b_out,
        out + (size_t)BATCH * DH);
}

// round 7
// speedup vs baseline: 1.4661x; 1.1837x over previous
#include <cuda_runtime.h>
#include <cstddef>
#include <cstdint>

#define BATCH 8192
#define NSEQ 50
#define NUM_NODES 200000
#define TD 16
#define DH 64
#define G3 192
#define RW 6           // batch rows per fused block
#define TC 5           // timesteps per chunk
#define THR 384
#define NB 32          // nodes per k_nodeQ block

typedef unsigned long long u64;

// ---------------- static device scratch ----------------
__device__ float g_P[(size_t)NUM_NODES * DH];      // node_raw @ W_feat
__device__ float g_Q[(size_t)NUM_NODES * G3];      // node_raw @ (W_feat @ sWih^T)
__device__ float g_skill[NUM_NODES];
__device__ u64   g_Gp[32 * 256];                   // packed combined [Q|P] weight table
__device__ u64   g_M2[2 * 8 * G3];                 // packed M = W_ih @ W_time^T per side
__device__ float g_v[2 * 3 * G3];                  // v0 (const+bias), v1 (struct), v2 (edge)

// ---------------- packed f32x2 helpers ----------------
__device__ __forceinline__ u64 pack2(float lo, float hi) {
    u64 d; asm("mov.b64 %0, {%1, %2};" : "=l"(d) : "f"(lo), "f"(hi)); return d;
}
__device__ __forceinline__ void unpack2(u64 v, float& lo, float& hi) {
    asm("mov.b64 {%0, %1}, %2;" : "=f"(lo), "=f"(hi) : "l"(v));
}
__device__ __forceinline__ u64 ffma2(u64 a, u64 b, u64 c) {
    u64 d; asm("fma.rn.f32x2 %0, %1, %2, %3;" : "=l"(d) : "l"(a), "l"(b), "l"(c));
    return d;
}
__device__ __forceinline__ void lds_v2u64(uint32_t addr, u64& a, u64& b) {
    asm volatile("ld.shared.v2.b64 {%0, %1}, [%2];" : "=l"(a), "=l"(b) : "r"(addr));
}
__device__ __forceinline__ u64 lds_u64(uint32_t addr) {
    u64 a; asm volatile("ld.shared.b64 %0, [%1];" : "=l"(a) : "r"(addr)); return a;
}
__device__ __forceinline__ uint32_t smem_u32(const void* p) {
    return (uint32_t)__cvta_generic_to_shared(p);
}

// ---------------- math helpers ----------------
__device__ __forceinline__ float cos_acc(float x) {
    const double TP = 6.283185307179586476925287;
    const float C1 = 6.28125f;
    const float C2 = (float)(TP - (double)C1);
    const float C3 = (float)(TP - (double)C1 - (double)((float)(TP - (double)C1)));
    const float INV2PI = 0.15915494309189535f;
    float k = rintf(x * INV2PI);
    float r = fmaf(-k, C1, x);
    r = fmaf(-k, C2, r);
    r = fmaf(-k, C3, r);
    return __cosf(r);
}
__device__ __forceinline__ float sigmoid_(float x) { return 1.0f / (1.0f + __expf(-x)); }
__device__ __forceinline__ float tanh_(float x) {
    float e = __expf(2.0f * x);
    return (e - 1.0f) / (e + 1.0f);
}

// ---------------- K1: derived weight tables ----------------
// block 0: Gp = packed [64 x 256] table, col c<192: (W_feat @ sWih^T)[:,c], c>=192: W_feat[:,c-192]
// block 1: M2 / v0 / v1 / v2 for both sides
__global__ void __launch_bounds__(384) k_ww(
    const float* __restrict__ Wf, const float* __restrict__ sWih,
    const float* __restrict__ dWih, const float* __restrict__ sbih,
    const float* __restrict__ dbih, const float* __restrict__ Wt,
    const float* __restrict__ Wstr, const float* __restrict__ Wedg,
    const float* __restrict__ bf, const float* __restrict__ be,
    const float* __restrict__ bt, const float* __restrict__ bs)
{
    __shared__ float sm[4096];
    const int tid = threadIdx.x;
    if (blockIdx.x == 0) {
        for (int i = tid; i < 4096; i += 384) sm[i] = Wf[i];
        __syncthreads();
        if (tid < 256) {
            const int c = tid;
            if (c < 192) {
                float row[64];
                const float4* rp = (const float4*)(sWih + (size_t)c * 64);
#pragma unroll
                for (int q4 = 0; q4 < 16; q4++) {
                    float4 v = rp[q4];
                    row[4*q4] = v.x; row[4*q4+1] = v.y; row[4*q4+2] = v.z; row[4*q4+3] = v.w;
                }
#pragma unroll
                for (int q = 0; q < 32; q++) {
                    float a0 = 0.f, a1 = 0.f;
#pragma unroll
                    for (int j = 0; j < 64; j++) {
                        a0 = fmaf(row[j], sm[(2*q)*64 + j], a0);
                        a1 = fmaf(row[j], sm[(2*q+1)*64 + j], a1);
                    }
                    g_Gp[q * 256 + c] = pack2(a0, a1);
                }
            } else {
                const int m2 = c - 192;
#pragma unroll
                for (int q = 0; q < 32; q++)
                    g_Gp[q * 256 + c] = pack2(sm[(2*q)*64 + m2], sm[(2*q+1)*64 + m2]);
            }
        }
    } else {
        for (int i = tid; i < 1024; i += 384) sm[i] = Wt[i];
        if (tid < 64) {
            sm[1024 + tid] = Wstr[tid];
            sm[1088 + tid] = Wedg[tid];
            sm[1152 + tid] = be[tid] + bt[tid] + 2.f * bs[tid] + bf[tid];  // src C
            sm[1216 + tid] = be[tid] + bt[tid] + bs[tid];                  // dst C
        }
        __syncthreads();
        const int side = tid / G3, k = tid % G3;
        const float* Wih = side ? dWih : sWih;
        const float* bihp = side ? dbih : sbih;
        float row[64];
        const float4* rp = (const float4*)(Wih + (size_t)k * 64);
#pragma unroll
        for (int q4 = 0; q4 < 16; q4++) {
            float4 v = rp[q4];
            row[4*q4] = v.x; row[4*q4+1] = v.y; row[4*q4+2] = v.z; row[4*q4+3] = v.w;
        }
        float M[16];
#pragma unroll
        for (int kk = 0; kk < 16; kk++) {
            float a = 0.f;
#pragma unroll
            for (int j = 0; j < 64; j++) a = fmaf(row[j], sm[kk * 64 + j], a);
            M[kk] = a;
        }
        float v1 = 0.f, v2 = 0.f, v0 = bihp[k];
#pragma unroll
        for (int j = 0; j < 64; j++) {
            v1 = fmaf(row[j], sm[1024 + j], v1);
            v2 = fmaf(row[j], sm[1088 + j], v2);
            v0 = fmaf(row[j], sm[1152 + side * 64 + j], v0);
        }
#pragma unroll
        for (int q = 0; q < 8; q++)
            g_M2[(side * 8 + q) * G3 + k] = pack2(M[2*q], M[2*q+1]);
        g_v[(side * 3 + 0) * G3 + k] = v0;
        g_v[(side * 3 + 1) * G3 + k] = v1;
        g_v[(side * 3 + 2) * G3 + k] = v2;
    }
}

// ---------------- K2: per-node Q (192) + P (64) + skill tables ----------------
__global__ void __launch_bounds__(256) k_nodeQ(const float* __restrict__ nodef) {
    __shared__ __align__(16) float rows[NB][64];
    const int tid = threadIdx.x;
    const int n0 = blockIdx.x * NB;
    for (int i = tid; i < NB * 64; i += 256) ((float*)rows)[i] = nodef[(size_t)n0 * 64 + i];
    __syncthreads();
    u64 w[32];
#pragma unroll
    for (int q = 0; q < 32; q++) w[q] = g_Gp[q * 256 + tid];
    const uint32_t rb = smem_u32(rows);
#pragma unroll 2
    for (int nn = 0; nn < NB; nn++) {
        const uint32_t ra = rb + nn * 256;
        u64 a0 = 0ull, a1 = 0ull;
#pragma unroll
        for (int q = 0; q < 16; q++) {
            u64 p, qq;
            lds_v2u64(ra + q * 16, p, qq);
            a0 = ffma2(w[2*q], p, a0);
            a1 = ffma2(w[2*q+1], qq, a1);
        }
        float lo, hi, lo2, hi2;
        unpack2(a0, lo, hi); unpack2(a1, lo2, hi2);
        const float val = (lo + hi) + (lo2 + hi2);
        const int n = n0 + nn;
        if (tid < 192) g_Q[(size_t)n * G3 + tid] = val;
        else g_P[(size_t)n * 64 + (tid - 192)] = val;
    }
    if (tid < NB) g_skill[n0 + tid] = rows[tid][0];
}

// ---------------- fused gi + GRU kernel ----------------
struct SMF {
    float gi[TC][RW][G3];              // 23040
    float ghH[2][RW][G3];              //  9216
    u64   M2s[8][G3];                  // 12288
    __align__(16) float te[TC][RW][TD];//  1920
    __align__(16) float h[RW][DH];     //  1536
    float sf[RW][NSEQ];                //  1200
    float e0[RW][NSEQ];                //  1200
    float dt[RW][NSEQ];                //  1200
    int   nid[RW][NSEQ];               //  1200
    float tailv[DH];                   //   256
    float tw[TD], tb[TD];              //   128
};

template <bool HAS_NODE>
__global__ void __launch_bounds__(THR, 3) k_fused(
    const int* __restrict__ nbr_nid, const int* __restrict__ nbr_eid,
    const float* __restrict__ nbr_ts, const float* __restrict__ t_int,
    const int* __restrict__ other_ids, const int* __restrict__ epi_ids,
    const float* __restrict__ edge_raw, const float* __restrict__ W_time,
    const float* __restrict__ time_w, const float* __restrict__ time_b,
    const float* __restrict__ W_edge, const float* __restrict__ b_feat,
    const float* __restrict__ b_edge, const float* __restrict__ b_time,
    const float* __restrict__ W_hh, const float* __restrict__ b_hh,
    const u64* __restrict__ M2g, const float* __restrict__ vg,
    const float* __restrict__ W_out, const float* __restrict__ b_out,
    float* __restrict__ outp)
{
    extern __shared__ char smraw[];
    SMF* s = (SMF*)smraw;
    const int tid = threadIdx.x;
    const int b0 = blockIdx.x * RW;
    const int rows = min(RW, BATCH - b0);
    const int k = tid % G3, g = tid / G3;       // role A: split-K over 192 outputs
    const int rg = tid >> 6, j = tid & 63;      // role B: (row, feature)

    // persistent regs: W_hh half-row
    u64 w2[16];
    {
        const float4* wp = (const float4*)(W_hh + (size_t)k * 64 + g * 32);
#pragma unroll
        for (int q = 0; q < 8; q++) {
            float4 v = wp[q];
            w2[2*q] = pack2(v.x, v.y);
            w2[2*q+1] = pack2(v.z, v.w);
        }
    }
    const float bhh = g ? 0.f : b_hh[k];
    const float v0k = vg[k], v1k = vg[G3 + k], v2k = vg[2 * G3 + k];

    // ---- init ----
    for (int i = tid; i < 8 * G3; i += THR) ((u64*)s->M2s)[i] = M2g[i];
    if (tid < 64) {
        float tl = b_time[tid] + b_edge[tid] + edge_raw[0] * W_edge[tid];
        if (!HAS_NODE) tl += b_feat[tid];
#pragma unroll
        for (int kk = 0; kk < TD; kk++)
            tl = fmaf(cos_acc(time_b[kk]), W_time[kk * 64 + tid], tl);
        s->tailv[tid] = tl;
    } else if (tid < 80) {
        s->tw[tid - 64] = time_w[tid - 64];
        s->tb[tid - 64] = time_b[tid - 64];
    }
    for (int i = tid; i < RW * NSEQ; i += THR) {
        const int r = i / NSEQ, t = i - r * NSEQ;
        const int gr = b0 + r;
        const bool ok = r < rows;
        const int gidx = ok ? gr * NSEQ + t : t;
        const int nd = nbr_nid[gidx];
        const int oth = other_ids[ok ? gr : b0];
        float sfv = (nd == oth) ? 1.f : 0.f;
        if (HAS_NODE) sfv += ((int)g_skill[nd] == (int)g_skill[oth]) ? 1.f : 0.f;
        ((int*)s->nid)[i] = nd;
        ((float*)s->sf)[i] = sfv;
        ((float*)s->e0)[i] = edge_raw[(size_t)nbr_eid[gidx] * 4];
        ((float*)s->dt)[i] = ok ? (t_int[gr] - nbr_ts[gidx]) : 0.f;
    }
    for (int i = tid; i < RW * DH; i += THR) ((float*)s->h)[i] = 0.f;
    __syncthreads();

    const uint32_t teb = smem_u32(s->te);
    const uint32_t hb = smem_u32(s->h);
    const uint32_t m2b = smem_u32(s->M2s) + (uint32_t)k * 8;

    for (int c = 0; c < NSEQ / TC; c++) {
        const int tb_ = c * TC;
        // (1) time encodings
        for (int i = tid; i < TC * RW * TD; i += THR) {
            const int kk = i & 15, p = i >> 4;
            const int rr = p % RW, ii = p / RW;
            s->te[ii][rr][kk] =
                cos_acc(__fadd_rn(__fmul_rn(s->dt[rr][tb_ + ii], s->tw[kk]), s->tb[kk]));
        }
        __syncthreads();
        // (2) gi build: gi = v0 + sf*v1 + e0*v2 + M@te (+ Q gather for src)
        {
            int p = g;
            float qv = 0.f;
            if (HAS_NODE) qv = g_Q[(size_t)s->nid[p % RW][tb_ + p / RW] * G3 + k];
#pragma unroll
            for (int pp = 0; pp < 15; pp++) {
                const int r = p % RW, ii = p / RW;
                const int p2 = p + 2;
                float qn = 0.f;
                if (HAS_NODE && pp < 14)
                    qn = g_Q[(size_t)s->nid[p2 % RW][tb_ + p2 / RW] * G3 + k];
                const uint32_t ta = teb + (uint32_t)(ii * RW + r) * 64;
                u64 A = 0ull, B = 0ull;
#pragma unroll
                for (int q = 0; q < 4; q++) {
                    u64 t0, t1;
                    lds_v2u64(ta + q * 16, t0, t1);
                    u64 m0 = lds_u64(m2b + (2 * q) * G3 * 8);
                    u64 m1 = lds_u64(m2b + (2 * q + 1) * G3 * 8);
                    A = ffma2(m0, t0, A);
                    B = ffma2(m1, t1, B);
                }
                float lo, hi, lo2, hi2;
                unpack2(A, lo, hi); unpack2(B, lo2, hi2);
                const float base =
                    fmaf(s->sf[r][tb_ + ii], v1k, fmaf(s->e0[r][tb_ + ii], v2k, v0k));
                s->gi[ii][r][k] = base + qv + ((lo + hi) + (lo2 + hi2));
                qv = qn; p = p2;
            }
        }
        __syncthreads();
        // (3) recurrence, TC steps
        for (int ii = 0; ii < TC; ii++) {
#pragma unroll
            for (int r = 0; r < RW; r++) {
                if (r < rows) {
                    const uint32_t ha = hb + (uint32_t)r * 256 + (uint32_t)g * 128;
                    u64 a0 = 0ull, a1 = 0ull;
#pragma unroll
                    for (int q = 0; q < 8; q++) {
                        u64 p_, q_;
                        lds_v2u64(ha + q * 16, p_, q_);
                        a0 = ffma2(w2[2*q], p_, a0);
                        a1 = ffma2(w2[2*q+1], q_, a1);
                    }
                    float lo, hi, lo2, hi2;
                    unpack2(a0, lo, hi); unpack2(a1, lo2, hi2);
                    s->ghH[g][r][k] = bhh + ((lo + hi) + (lo2 + hi2));
                }
            }
            __syncthreads();
            if (rg < rows) {
                const float gir = s->gi[ii][rg][j];
                const float giz = s->gi[ii][rg][64 + j];
                const float gin = s->gi[ii][rg][128 + j];
                const float ghr = s->ghH[0][rg][j] + s->ghH[1][rg][j];
                const float ghz = s->ghH[0][rg][64 + j] + s->ghH[1][rg][64 + j];
                const float ghn = s->ghH[0][rg][128 + j] + s->ghH[1][rg][128 + j];
                const float r_ = sigmoid_(gir + ghr);
                const float z_ = sigmoid_(giz + ghz);
                const float n_ = tanh_(fmaf(r_, ghn, gin));
                const float ho = s->h[rg][j];
                s->h[rg][j] = (1.f - z_) * n_ + z_ * ho;
            }
            __syncthreads();
        }
    }

    // ---- epilogue ----
    if (rg < rows) {
        float e = s->h[rg][j] + s->tailv[j];
        if (!HAS_NODE) e += g_P[(size_t)epi_ids[b0 + rg] * 64 + j];
        s->gi[0][rg][j] = e;
    }
    __syncthreads();
    if (rg < rows) {
        float acc = b_out[j];
        const float* em = s->gi[0][rg];
#pragma unroll 8
        for (int m = 0; m < 64; m++) acc = fmaf(em[m], W_out[m * 64 + j], acc);
        outp[(size_t)(b0 + rg) * 64 + j] = acc;
    }
}

// ---------------- launch ----------------
extern "C" void kernel_launch(void* const* d_in, const int* in_sizes, int n_in,
                              void* d_out, int out_size) {
    const float* node_raw = (const float*)d_in[0];
    const float* edge_raw = (const float*)d_in[1];
    const int* src_ids = (const int*)d_in[2];
    const int* dst_ids = (const int*)d_in[3];
    const float* t_int = (const float*)d_in[4];
    const int* s_nnid = (const int*)d_in[5];
    const int* s_neid = (const int*)d_in[6];
    const float* s_nts = (const float*)d_in[7];
    const int* d_nnid = (const int*)d_in[8];
    const int* d_neid = (const int*)d_in[9];
    const float* d_nts = (const float*)d_in[10];
    const float* W_feat = (const float*)d_in[11];
    const float* b_feat = (const float*)d_in[12];
    const float* W_edge = (const float*)d_in[13];
    const float* b_edge = (const float*)d_in[14];
    const float* W_time = (const float*)d_in[15];
    const float* b_time = (const float*)d_in[16];
    const float* W_struct = (const float*)d_in[17];
    const float* b_struct = (const float*)d_in[18];
    const float* W_out = (const float*)d_in[19];
    const float* b_out = (const float*)d_in[20];
    const float* time_w = (const float*)d_in[21];
    const float* time_b = (const float*)d_in[22];
    const float* sWih = (const float*)d_in[23];
    const float* sWhh = (const float*)d_in[24];
    const float* sbih = (const float*)d_in[25];
    const float* sbhh = (const float*)d_in[26];
    const float* dWih = (const float*)d_in[27];
    const float* dWhh = (const float*)d_in[28];
    const float* dbih = (const float*)d_in[29];
    const float* dbhh = (const float*)d_in[30];

    float* out = (float*)d_out;

    u64* M2_p; cudaGetSymbolAddress((void**)&M2_p, g_M2);
    float* v_p; cudaGetSymbolAddress((void**)&v_p, g_v);

    const int smem = (int)sizeof(SMF);
    cudaFuncSetAttribute(k_fused<true>, cudaFuncAttributeMaxDynamicSharedMemorySize, smem);
    cudaFuncSetAttribute(k_fused<false>, cudaFuncAttributeMaxDynamicSharedMemorySize, smem);

    // prep: derived weights, then node tables
    k_ww<<<2, 384>>>(W_feat, sWih, dWih, sbih, dbih, W_time, W_struct, W_edge,
                     b_feat, b_edge, b_time, b_struct);
    k_nodeQ<<<NUM_NODES / NB, 256>>>(node_raw);

    const int grid = (BATCH + RW - 1) / RW;
    // src side: Q gather + skill/co struct; tail without b_feat
    k_fused<true><<<grid, THR, smem>>>(
        s_nnid, s_neid, s_nts, t_int, dst_ids, dst_ids, edge_raw,
        W_time, time_w, time_b, W_edge, b_feat, b_edge, b_time,
        sWhh, sbhh, M2_p, v_p, W_out, b_out, out);
    // dst side: no node term in gi; epilogue adds b_feat (in tail) + P[dst]
    k_fused<false><<<grid, THR, smem>>>(
        d_nnid, d_neid, d_nts, t_int, src_ids, dst_ids, edge_raw,
        W_time, time_w, time_b, W_edge, b_feat, b_edge, b_time,
        dWhh, dbhh, M2_p + 8 * G3, v_p + 3 * G3, W_out, b_out,
        out + (size_t)BATCH * DH);
}

// round 8
// speedup vs baseline: 1.5753x; 1.0745x over previous
#include <cuda_runtime.h>
#include <cstddef>
#include <cstdint>

#define BATCH 8192
#define NSEQ 50
#define NUM_NODES 200000
#define TD 16
#define DH 64
#define G3 192
#define RW 6           // batch rows per fused block
#define TC 5           // timesteps per chunk
#define THR 384
#define NB 32          // nodes per k_nodeQ block

typedef unsigned long long u64;

// ---------------- static device scratch ----------------
__device__ float g_P[(size_t)NUM_NODES * DH];      // node_raw @ W_feat
__device__ float g_Q[(size_t)NUM_NODES * G3];      // node_raw @ (W_feat @ sWih^T)
__device__ float g_skill[NUM_NODES];
__device__ u64   g_Gp[32 * 256];                   // packed combined [Q|P] weight table
__device__ u64   g_M2[2 * 8 * G3];                 // packed M = W_ih @ W_time^T per side
__device__ float g_v[2 * 3 * G3];                  // v0 (const+bias), v1 (struct), v2 (edge)

// ---------------- packed f32x2 helpers ----------------
__device__ __forceinline__ u64 pack2(float lo, float hi) {
    u64 d; asm("mov.b64 %0, {%1, %2};" : "=l"(d) : "f"(lo), "f"(hi)); return d;
}
__device__ __forceinline__ void unpack2(u64 v, float& lo, float& hi) {
    asm("mov.b64 {%0, %1}, %2;" : "=f"(lo), "=f"(hi) : "l"(v));
}
__device__ __forceinline__ u64 ffma2(u64 a, u64 b, u64 c) {
    u64 d; asm("fma.rn.f32x2 %0, %1, %2, %3;" : "=l"(d) : "l"(a), "l"(b), "l"(c));
    return d;
}
__device__ __forceinline__ void lds_v2u64(uint32_t addr, u64& a, u64& b) {
    asm volatile("ld.shared.v2.b64 {%0, %1}, [%2];" : "=l"(a), "=l"(b) : "r"(addr));
}
__device__ __forceinline__ u64 lds_u64(uint32_t addr) {
    u64 a; asm volatile("ld.shared.b64 %0, [%1];" : "=l"(a) : "r"(addr)); return a;
}
__device__ __forceinline__ uint32_t smem_u32(const void* p) {
    return (uint32_t)__cvta_generic_to_shared(p);
}

// ---------------- math helpers ----------------
__device__ __forceinline__ float cos_acc(float x) {
    const double TP = 6.283185307179586476925287;
    const float C1 = 6.28125f;
    const float C2 = (float)(TP - (double)C1);
    const float C3 = (float)(TP - (double)C1 - (double)((float)(TP - (double)C1)));
    const float INV2PI = 0.15915494309189535f;
    float k = rintf(x * INV2PI);
    float r = fmaf(-k, C1, x);
    r = fmaf(-k, C2, r);
    r = fmaf(-k, C3, r);
    return __cosf(r);
}
// fast-approx gates: MUFU.RCP via __fdividef (<=2 ulp), EX2 via __expf
__device__ __forceinline__ float sigmoid_(float x) {
    float e = __expf(-x);
    return __fdividef(1.0f, 1.0f + e);
}
__device__ __forceinline__ float tanh_(float x) {
    float e = __expf(-2.0f * x);
    return __fdividef(2.0f, 1.0f + e) - 1.0f;
}

// ---------------- K1: derived weight tables ----------------
__global__ void __launch_bounds__(384) k_ww(
    const float* __restrict__ Wf, const float* __restrict__ sWih,
    const float* __restrict__ dWih, const float* __restrict__ sbih,
    const float* __restrict__ dbih, const float* __restrict__ Wt,
    const float* __restrict__ Wstr, const float* __restrict__ Wedg,
    const float* __restrict__ bf, const float* __restrict__ be,
    const float* __restrict__ bt, const float* __restrict__ bs)
{
    __shared__ float sm[4096];
    const int tid = threadIdx.x;
    if (blockIdx.x == 0) {
        for (int i = tid; i < 4096; i += 384) sm[i] = Wf[i];
        __syncthreads();
        if (tid < 256) {
            const int c = tid;
            if (c < 192) {
                float row[64];
                const float4* rp = (const float4*)(sWih + (size_t)c * 64);
#pragma unroll
                for (int q4 = 0; q4 < 16; q4++) {
                    float4 v = rp[q4];
                    row[4*q4] = v.x; row[4*q4+1] = v.y; row[4*q4+2] = v.z; row[4*q4+3] = v.w;
                }
#pragma unroll
                for (int q = 0; q < 32; q++) {
                    float a0 = 0.f, a1 = 0.f;
#pragma unroll
                    for (int j = 0; j < 64; j++) {
                        a0 = fmaf(row[j], sm[(2*q)*64 + j], a0);
                        a1 = fmaf(row[j], sm[(2*q+1)*64 + j], a1);
                    }
                    g_Gp[q * 256 + c] = pack2(a0, a1);
                }
            } else {
                const int m2 = c - 192;
#pragma unroll
                for (int q = 0; q < 32; q++)
                    g_Gp[q * 256 + c] = pack2(sm[(2*q)*64 + m2], sm[(2*q+1)*64 + m2]);
            }
        }
    } else {
        for (int i = tid; i < 1024; i += 384) sm[i] = Wt[i];
        if (tid < 64) {
            sm[1024 + tid] = Wstr[tid];
            sm[1088 + tid] = Wedg[tid];
            sm[1152 + tid] = be[tid] + bt[tid] + 2.f * bs[tid] + bf[tid];  // src C
            sm[1216 + tid] = be[tid] + bt[tid] + bs[tid];                  // dst C
        }
        __syncthreads();
        const int side = tid / G3, k = tid % G3;
        const float* Wih = side ? dWih : sWih;
        const float* bihp = side ? dbih : sbih;
        float row[64];
        const float4* rp = (const float4*)(Wih + (size_t)k * 64);
#pragma unroll
        for (int q4 = 0; q4 < 16; q4++) {
            float4 v = rp[q4];
            row[4*q4] = v.x; row[4*q4+1] = v.y; row[4*q4+2] = v.z; row[4*q4+3] = v.w;
        }
        float M[16];
#pragma unroll
        for (int kk = 0; kk < 16; kk++) {
            float a = 0.f;
#pragma unroll
            for (int j = 0; j < 64; j++) a = fmaf(row[j], sm[kk * 64 + j], a);
            M[kk] = a;
        }
        float v1 = 0.f, v2 = 0.f, v0 = bihp[k];
#pragma unroll
        for (int j = 0; j < 64; j++) {
            v1 = fmaf(row[j], sm[1024 + j], v1);
            v2 = fmaf(row[j], sm[1088 + j], v2);
            v0 = fmaf(row[j], sm[1152 + side * 64 + j], v0);
        }
#pragma unroll
        for (int q = 0; q < 8; q++)
            g_M2[(side * 8 + q) * G3 + k] = pack2(M[2*q], M[2*q+1]);
        g_v[(side * 3 + 0) * G3 + k] = v0;
        g_v[(side * 3 + 1) * G3 + k] = v1;
        g_v[(side * 3 + 2) * G3 + k] = v2;
    }
}

// ---------------- K2: per-node Q (192) + P (64) + skill tables ----------------
__global__ void __launch_bounds__(256) k_nodeQ(const float* __restrict__ nodef) {
    __shared__ __align__(16) float rows[NB][64];
    const int tid = threadIdx.x;
    const int n0 = blockIdx.x * NB;
    for (int i = tid; i < NB * 64; i += 256) ((float*)rows)[i] = nodef[(size_t)n0 * 64 + i];
    __syncthreads();
    u64 w[32];
#pragma unroll
    for (int q = 0; q < 32; q++) w[q] = g_Gp[q * 256 + tid];
    const uint32_t rb = smem_u32(rows);
#pragma unroll 2
    for (int nn = 0; nn < NB; nn++) {
        const uint32_t ra = rb + nn * 256;
        u64 a0 = 0ull, a1 = 0ull;
#pragma unroll
        for (int q = 0; q < 16; q++) {
            u64 p, qq;
            lds_v2u64(ra + q * 16, p, qq);
            a0 = ffma2(w[2*q], p, a0);
            a1 = ffma2(w[2*q+1], qq, a1);
        }
        float lo, hi, lo2, hi2;
        unpack2(a0, lo, hi); unpack2(a1, lo2, hi2);
        const float val = (lo + hi) + (lo2 + hi2);
        const int n = n0 + nn;
        if (tid < 192) g_Q[(size_t)n * G3 + tid] = val;
        else g_P[(size_t)n * 64 + (tid - 192)] = val;
    }
    if (tid < NB) g_skill[n0 + tid] = rows[tid][0];
}

// ---------------- fused gi + GRU kernel ----------------
struct SMF {
    float gi[TC][RW][G3];              // 23040
    float ghP[RW][G3][2];              //  9216 : gh halves interleaved
    u64   M2s[8][G3];                  // 12288
    __align__(16) float te[TC][RW][TD];//  1920
    __align__(16) float h[RW][DH];     //  1536
    float sf[RW][NSEQ];                //  1200
    float e0[RW][NSEQ];                //  1200
    float dt[RW][NSEQ];                //  1200
    int   nid[RW][NSEQ];               //  1200
    float tailv[DH];                   //   256
    float tw[TD], tb[TD];              //   128
};

template <bool HAS_NODE>
__global__ void __launch_bounds__(THR, 3) k_fused(
    const int* __restrict__ nbr_nid, const int* __restrict__ nbr_eid,
    const float* __restrict__ nbr_ts, const float* __restrict__ t_int,
    const int* __restrict__ other_ids, const int* __restrict__ epi_ids,
    const float* __restrict__ edge_raw, const float* __restrict__ W_time,
    const float* __restrict__ time_w, const float* __restrict__ time_b,
    const float* __restrict__ W_edge, const float* __restrict__ b_feat,
    const float* __restrict__ b_edge, const float* __restrict__ b_time,
    const float* __restrict__ W_hh, const float* __restrict__ b_hh,
    const u64* __restrict__ M2g, const float* __restrict__ vg,
    const float* __restrict__ W_out, const float* __restrict__ b_out,
    float* __restrict__ outp)
{
    extern __shared__ char smraw[];
    SMF* s = (SMF*)smraw;
    const int tid = threadIdx.x;
    const int b0 = blockIdx.x * RW;
    const int rows = min(RW, BATCH - b0);
    const int k = tid % G3, g = tid / G3;       // role A: split-K over 192 outputs
    const int rg = tid >> 6, j = tid & 63;      // role B: (row, feature)

    // persistent regs: W_hh half-row + packed bias init
    u64 w2[16];
    {
        const float4* wp = (const float4*)(W_hh + (size_t)k * 64 + g * 32);
#pragma unroll
        for (int q = 0; q < 8; q++) {
            float4 v = wp[q];
            w2[2*q] = pack2(v.x, v.y);
            w2[2*q+1] = pack2(v.z, v.w);
        }
    }
    const u64 binit = g ? 0ull : pack2(b_hh[k], 0.f);
    const float v0k = vg[k], v1k = vg[G3 + k], v2k = vg[2 * G3 + k];

    // ---- init ----
    for (int i = tid; i < 8 * G3; i += THR) ((u64*)s->M2s)[i] = M2g[i];
    if (tid < 64) {
        float tl = b_time[tid] + b_edge[tid] + edge_raw[0] * W_edge[tid];
        if (!HAS_NODE) tl += b_feat[tid];
#pragma unroll
        for (int kk = 0; kk < TD; kk++)
            tl = fmaf(cos_acc(time_b[kk]), W_time[kk * 64 + tid], tl);
        s->tailv[tid] = tl;
    } else if (tid < 80) {
        s->tw[tid - 64] = time_w[tid - 64];
        s->tb[tid - 64] = time_b[tid - 64];
    }
    for (int i = tid; i < RW * NSEQ; i += THR) {
        const int r = i / NSEQ, t = i - r * NSEQ;
        const int gr = b0 + r;
        const bool ok = r < rows;
        const int gidx = ok ? gr * NSEQ + t : t;
        const int nd = nbr_nid[gidx];
        const int oth = other_ids[ok ? gr : b0];
        float sfv = (nd == oth) ? 1.f : 0.f;
        if (HAS_NODE) sfv += ((int)g_skill[nd] == (int)g_skill[oth]) ? 1.f : 0.f;
        ((int*)s->nid)[i] = nd;
        ((float*)s->sf)[i] = sfv;
        ((float*)s->e0)[i] = edge_raw[(size_t)nbr_eid[gidx] * 4];
        ((float*)s->dt)[i] = ok ? (t_int[gr] - nbr_ts[gidx]) : 0.f;
    }
    for (int i = tid; i < RW * DH; i += THR) ((float*)s->h)[i] = 0.f;
    float hreg = 0.f;                            // role-B private h element
    __syncthreads();

    const uint32_t teb = smem_u32(s->te);
    const uint32_t hb = smem_u32(s->h) + (uint32_t)g * 128;
    const uint32_t m2b = smem_u32(s->M2s) + (uint32_t)k * 8;
    const float2* ghv = (const float2*)s->ghP[rg];

    for (int c = 0; c < NSEQ / TC; c++) {
        const int tb_ = c * TC;
        // (1) time encodings
        for (int i = tid; i < TC * RW * TD; i += THR) {
            const int kk = i & 15, p = i >> 4;
            const int rr = p % RW, ii = p / RW;
            s->te[ii][rr][kk] =
                cos_acc(__fadd_rn(__fmul_rn(s->dt[rr][tb_ + ii], s->tw[kk]), s->tb[kk]));
        }
        __syncthreads();
        // (2) gi build: gi = v0 + sf*v1 + e0*v2 + M@te (+ Q gather for src)
        {
            int p = g;
            float qv = 0.f;
            if (HAS_NODE) qv = g_Q[(size_t)s->nid[p % RW][tb_ + p / RW] * G3 + k];
#pragma unroll
            for (int pp = 0; pp < 15; pp++) {
                const int r = p % RW, ii = p / RW;
                const int p2 = p + 2;
                float qn = 0.f;
                if (HAS_NODE && pp < 14)
                    qn = g_Q[(size_t)s->nid[p2 % RW][tb_ + p2 / RW] * G3 + k];
                const uint32_t ta = teb + (uint32_t)(ii * RW + r) * 64;
                u64 A = 0ull, B = 0ull;
#pragma unroll
                for (int q = 0; q < 4; q++) {
                    u64 t0, t1;
                    lds_v2u64(ta + q * 16, t0, t1);
                    u64 m0 = lds_u64(m2b + (2 * q) * G3 * 8);
                    u64 m1 = lds_u64(m2b + (2 * q + 1) * G3 * 8);
                    A = ffma2(m0, t0, A);
                    B = ffma2(m1, t1, B);
                }
                float lo, hi, lo2, hi2;
                unpack2(A, lo, hi); unpack2(B, lo2, hi2);
                const float base =
                    fmaf(s->sf[r][tb_ + ii], v1k, fmaf(s->e0[r][tb_ + ii], v2k, v0k));
                s->gi[ii][r][k] = base + qv + ((lo + hi) + (lo2 + hi2));
                qv = qn; p = p2;
            }
        }
        __syncthreads();
        // (3) recurrence, TC steps
        for (int ii = 0; ii < TC; ii++) {
            // gh half-dots, rows paired for ILP; no row guards (h zero-padded)
#pragma unroll
            for (int r = 0; r < RW; r += 2) {
                const uint32_t ha = hb + (uint32_t)r * 256;
                u64 a0 = binit, a1 = 0ull, c0 = binit, c1 = 0ull;
#pragma unroll
                for (int q = 0; q < 8; q++) {
                    u64 p_, q_, p2_, q2_;
                    lds_v2u64(ha + q * 16, p_, q_);
                    lds_v2u64(ha + 256 + q * 16, p2_, q2_);
                    a0 = ffma2(w2[2*q], p_, a0);
                    a1 = ffma2(w2[2*q+1], q_, a1);
                    c0 = ffma2(w2[2*q], p2_, c0);
                    c1 = ffma2(w2[2*q+1], q2_, c1);
                }
                float lo, hi, lo2, hi2;
                unpack2(a0, lo, hi); unpack2(a1, lo2, hi2);
                s->ghP[r][k][g] = (lo + hi) + (lo2 + hi2);
                unpack2(c0, lo, hi); unpack2(c1, lo2, hi2);
                s->ghP[r + 1][k][g] = (lo + hi) + (lo2 + hi2);
            }
            __syncthreads();
            // gates + h update (role B); h kept in register
            {
                const float2 rr2 = ghv[j];
                const float2 zz2 = ghv[64 + j];
                const float2 nn2 = ghv[128 + j];
                const float gir = s->gi[ii][rg][j];
                const float giz = s->gi[ii][rg][64 + j];
                const float gin = s->gi[ii][rg][128 + j];
                const float r_ = sigmoid_(gir + rr2.x + rr2.y);
                const float z_ = sigmoid_(giz + zz2.x + zz2.y);
                const float n_ = tanh_(fmaf(r_, nn2.x + nn2.y, gin));
                hreg = fmaf(z_, hreg - n_, n_);
                s->h[rg][j] = hreg;
            }
            __syncthreads();
        }
    }

    // ---- epilogue ----
    {
        float e = hreg + s->tailv[j];
        if (!HAS_NODE) e += g_P[(size_t)epi_ids[b0 + ((rg < rows) ? rg : 0)] * 64 + j];
        s->gi[0][rg][j] = e;
    }
    __syncthreads();
    if (rg < rows) {
        float acc = b_out[j];
        const float* em = s->gi[0][rg];
#pragma unroll 8
        for (int m = 0; m < 64; m++) acc = fmaf(em[m], W_out[m * 64 + j], acc);
        outp[(size_t)(b0 + rg) * 64 + j] = acc;
    }
}

// ---------------- launch ----------------
extern "C" void kernel_launch(void* const* d_in, const int* in_sizes, int n_in,
                              void* d_out, int out_size) {
    const float* node_raw = (const float*)d_in[0];
    const float* edge_raw = (const float*)d_in[1];
    const int* src_ids = (const int*)d_in[2];
    const int* dst_ids = (const int*)d_in[3];
    const float* t_int = (const float*)d_in[4];
    const int* s_nnid = (const int*)d_in[5];
    const int* s_neid = (const int*)d_in[6];
    const float* s_nts = (const float*)d_in[7];
    const int* d_nnid = (const int*)d_in[8];
    const int* d_neid = (const int*)d_in[9];
    const float* d_nts = (const float*)d_in[10];
    const float* W_feat = (const float*)d_in[11];
    const float* b_feat = (const float*)d_in[12];
    const float* W_edge = (const float*)d_in[13];
    const float* b_edge = (const float*)d_in[14];
    const float* W_time = (const float*)d_in[15];
    const float* b_time = (const float*)d_in[16];
    const float* W_struct = (const float*)d_in[17];
    const float* b_struct = (const float*)d_in[18];
    const float* W_out = (const float*)d_in[19];
    const float* b_out = (const float*)d_in[20];
    const float* time_w = (const float*)d_in[21];
    const float* time_b = (const float*)d_in[22];
    const float* sWih = (const float*)d_in[23];
    const float* sWhh = (const float*)d_in[24];
    const float* sbih = (const float*)d_in[25];
    const float* sbhh = (const float*)d_in[26];
    const float* dWih = (const float*)d_in[27];
    const float* dWhh = (const float*)d_in[28];
    const float* dbih = (const float*)d_in[29];
    const float* dbhh = (const float*)d_in[30];

    float* out = (float*)d_out;

    u64* M2_p; cudaGetSymbolAddress((void**)&M2_p, g_M2);
    float* v_p; cudaGetSymbolAddress((void**)&v_p, g_v);

    const int smem = (int)sizeof(SMF);
    cudaFuncSetAttribute(k_fused<true>, cudaFuncAttributeMaxDynamicSharedMemorySize, smem);
    cudaFuncSetAttribute(k_fused<false>, cudaFuncAttributeMaxDynamicSharedMemorySize, smem);

    k_ww<<<2, 384>>>(W_feat, sWih, dWih, sbih, dbih, W_time, W_struct, W_edge,
                     b_feat, b_edge, b_time, b_struct);
    k_nodeQ<<<NUM_NODES / NB, 256>>>(node_raw);

    const int grid = (BATCH + RW - 1) / RW;
    k_fused<true><<<grid, THR, smem>>>(
        s_nnid, s_neid, s_nts, t_int, dst_ids, dst_ids, edge_raw,
        W_time, time_w, time_b, W_edge, b_feat, b_edge, b_time,
        sWhh, sbhh, M2_p, v_p, W_out, b_out, out);
    k_fused<false><<<grid, THR, smem>>>(
        d_nnid, d_neid, d_nts, t_int, src_ids, dst_ids, edge_raw,
        W_time, time_w, time_b, W_edge, b_feat, b_edge, b_time,
        dWhh, dbhh, M2_p + 8 * G3, v_p + 3 * G3, W_out, b_out,
        out + (size_t)BATCH * DH);
}